// round 4
// baseline (speedup 1.0000x reference)
#include <cuda_runtime.h>
#include <cuda_fp16.h>
#include <math.h>

#define Nn 50000
#define Hh 128
#define Ee 800000
#define NGg 64
#define EPSc 1e-5f
#define NB_SCAN 196   // ceil(50000/256)

// ---------------- device scratch (static globals; no allocation) ----------------
__device__ int    g_is64;
__device__ int    d_src[Ee];
__device__ int    d_dst[Ee];
__device__ int    d_batch[Nn];
__device__ int    d_deg[Nn];
__device__ float  d_dis[Nn];
__device__ int    d_rowptr[Nn + 1];
__device__ int    d_cursor[Nn];
__device__ int    d_col[Ee];
__device__ float  d_w[Ee];
__device__ unsigned long long d_scan_state[NB_SCAN];
__device__ unsigned d_ticket;
__device__ int    d_gstart[NGg + 1];
__device__ float  d_gcntf[NGg];
__device__ float  d_mean[NGg * Hh];
__device__ float  d_var[NGg * Hh];
__device__ float  d_HA[(size_t)Nn * Hh];
__device__ float  d_HB[(size_t)Nn * Hh];
__device__ __half d_Th[(size_t)Nn * Hh];
__device__ float  d_A[(size_t)Nn * Hh];

// ---------------- preprocessing ----------------

// zero degree array + scan state + ticket, and detect index dtype
__global__ void zero_detect_kernel(const void* ei) {
    int i = blockIdx.x * blockDim.x + threadIdx.x;
    if (i < Nn) d_deg[i] = 0;
    if (i < NB_SCAN) d_scan_state[i] = 0ull;
    if (i == 0) {
        d_ticket = 0u;
        const long long* p = (const long long*)ei;
        int ok = 1;
        for (int k = 0; k < 64; k++) {
            long long v = p[k];
            if (v < 0 || v >= (long long)Nn) ok = 0;
        }
        g_is64 = ok;
    }
}

// fused: convert edge_index + batch to int32, histogram dst degrees
__global__ void convert_hist_kernel(const void* ei, const void* bt) {
    int is64 = g_is64;
    int stride = gridDim.x * blockDim.x;
    for (int i = blockIdx.x * blockDim.x + threadIdx.x; i < 2 * Ee; i += stride) {
        int v = is64 ? (int)((const long long*)ei)[i] : ((const int*)ei)[i];
        if (i < Ee) d_src[i] = v;
        else { d_dst[i - Ee] = v; atomicAdd(&d_deg[v], 1); }
    }
    for (int i = blockIdx.x * blockDim.x + threadIdx.x; i < Nn; i += stride) {
        int v = is64 ? (int)((const long long*)bt)[i] : ((const int*)bt)[i];
        d_batch[i] = v;
    }
}

// single-kernel decoupled-lookback scan of d_deg -> rowptr/cursor/dis,
// plus per-graph ranges (block 0).
__global__ void scan_fused_kernel() {
    __shared__ unsigned sbid;
    __shared__ int s_excl;
    __shared__ int sh[256];
    if (threadIdx.x == 0) sbid = atomicAdd(&d_ticket, 1u);
    __syncthreads();
    int b = (int)sbid;
    int idx = b * 256 + threadIdx.x;
    int deg = (idx < Nn) ? d_deg[idx] : 0;
    sh[threadIdx.x] = deg;
    __syncthreads();
    for (int off = 1; off < 256; off <<= 1) {
        int u = 0;
        if (threadIdx.x >= off) u = sh[threadIdx.x - off];
        __syncthreads();
        if (threadIdx.x >= off) sh[threadIdx.x] += u;
        __syncthreads();
    }
    int incl = sh[threadIdx.x];
    int aggr = sh[255];
    if (threadIdx.x == 0) {
        if (b == 0) {
            atomicExch(&d_scan_state[0], (2ull << 32) | (unsigned)aggr);
            s_excl = 0;
        } else {
            atomicExch(&d_scan_state[b], (1ull << 32) | (unsigned)aggr);
            int excl = 0;
            int j = b - 1;
            while (true) {
                unsigned long long st;
                do { st = atomicAdd(&d_scan_state[j], 0ull); } while ((st >> 32) == 0ull);
                excl += (int)(unsigned)st;
                if ((st >> 32) == 2ull) break;
                j--;
            }
            atomicExch(&d_scan_state[b], (2ull << 32) | (unsigned)(excl + aggr));
            s_excl = excl;
        }
    }
    __syncthreads();
    int excl = s_excl;
    if (idx < Nn) {
        d_rowptr[idx + 1] = excl + incl;
        if (idx == 0) d_rowptr[0] = 0;
        d_cursor[idx] = excl + incl - deg;
        d_dis[idx] = rsqrtf((float)deg + 1.0f);
    }
    // block 0 additionally computes per-graph node ranges (batch is sorted)
    if (b == 0) {
        int t = threadIdx.x;
        if (t <= NGg) {
            int lo = 0, hi = Nn;
            while (lo < hi) {
                int mid = (lo + hi) >> 1;
                if (d_batch[mid] < t) lo = mid + 1; else hi = mid;
            }
            d_gstart[t] = lo;
        }
        __syncthreads();
        if (t < NGg) {
            int c = d_gstart[t + 1] - d_gstart[t];
            d_gcntf[t] = (c > 0) ? (float)c : 1.0f;
        }
    }
}

__global__ void scatter_kernel() {
    int i = blockIdx.x * blockDim.x + threadIdx.x;
    if (i >= Ee) return;
    int s = d_src[i], dd = d_dst[i];
    int pos = atomicAdd(&d_cursor[dd], 1);
    d_col[pos] = s;
    d_w[pos] = d_dis[s] * d_dis[dd];
}

// ---------------- tf32 tensor-core GEMM with optional fused GraphNorm ---------
#define XS_LD 132
#define WS_LD 136

__device__ __forceinline__ float tfq(float v) {
    unsigned o;
    asm("cvt.rna.tf32.f32 %0, %1;" : "=r"(o) : "f"(v));
    return __uint_as_float(o);
}

// normalized row chunk: relu((A - alpha*mean)*rsqrt(var+eps)*gamma + beta) [+ resid]
template <int RES>
__device__ __forceinline__ float4 norm_row4(
    const float* __restrict__ A, const float* __restrict__ resid,
    const float* __restrict__ alpha, const float* __restrict__ gamma,
    const float* __restrict__ beta, int gr, int c) {
    int g = d_batch[gr];
    float4 a  = *(const float4*)&A[(size_t)gr * 128 + c];
    float4 m  = *(const float4*)&d_mean[g * 128 + c];
    float4 vv = *(const float4*)&d_var[g * 128 + c];
    float4 al = *(const float4*)&alpha[c];
    float4 ga = *(const float4*)&gamma[c];
    float4 be = *(const float4*)&beta[c];
    float4 o;
    o.x = fmaxf((a.x - al.x * m.x) * rsqrtf(vv.x + EPSc) * ga.x + be.x, 0.f);
    o.y = fmaxf((a.y - al.y * m.y) * rsqrtf(vv.y + EPSc) * ga.y + be.y, 0.f);
    o.z = fmaxf((a.z - al.z * m.z) * rsqrtf(vv.z + EPSc) * ga.z + be.z, 0.f);
    o.w = fmaxf((a.w - al.w * m.w) * rsqrtf(vv.w + EPSc) * ga.w + be.w, 0.f);
    if (RES) {
        float4 r = *(const float4*)&resid[(size_t)gr * 128 + c];
        o.x += r.x; o.y += r.y; o.z += r.z; o.w += r.w;
    }
    return o;
}

// prologue: stage W and (optionally normalized) X into smem as tf32
template <int NORM, int RES, int STORE>
__device__ __forceinline__ void load_tiles(
    const float* __restrict__ X, const float* __restrict__ resid,
    const float* __restrict__ alpha, const float* __restrict__ gamma,
    const float* __restrict__ beta, const float* __restrict__ W,
    float* __restrict__ Hout, int n, int row0, float* Xs, float* Ws) {
    int tid = threadIdx.x;
#pragma unroll
    for (int i = 0; i < 16; i++) {
        int idx = i * 256 + tid;
        int r = idx >> 5;
        int c = (idx & 31) * 4;
        float4 wv = *(const float4*)&W[r * 128 + c];
        Ws[r * WS_LD + c + 0] = tfq(wv.x);
        Ws[r * WS_LD + c + 1] = tfq(wv.y);
        Ws[r * WS_LD + c + 2] = tfq(wv.z);
        Ws[r * WS_LD + c + 3] = tfq(wv.w);
        int gr = row0 + r;
        float4 xv = make_float4(0.f, 0.f, 0.f, 0.f);
        if (gr < n) {
            if (NORM) {
                xv = norm_row4<RES>(X, resid, alpha, gamma, beta, gr, c);
                if (STORE) *(float4*)&Hout[(size_t)gr * 128 + c] = xv;
            } else {
                xv = *(const float4*)&X[(size_t)gr * 128 + c];
            }
        }
        Xs[r * XS_LD + c + 0] = tfq(xv.x);
        Xs[r * XS_LD + c + 1] = tfq(xv.y);
        Xs[r * XS_LD + c + 2] = tfq(xv.z);
        Xs[r * XS_LD + c + 3] = tfq(xv.w);
    }
    __syncthreads();
}

__device__ __forceinline__ void mma_core(const float* Xs, const float* Ws,
                                         int m0, int qr, int qc, float acc[16][4]) {
#pragma unroll
    for (int t = 0; t < 16; t++) {
        acc[t][0] = 0.f; acc[t][1] = 0.f; acc[t][2] = 0.f; acc[t][3] = 0.f;
    }
#pragma unroll 4
    for (int k0 = 0; k0 < 128; k0 += 8) {
        unsigned a0 = __float_as_uint(Xs[(m0 + qr)     * XS_LD + k0 + qc]);
        unsigned a1 = __float_as_uint(Xs[(m0 + qr + 8) * XS_LD + k0 + qc]);
        unsigned a2 = __float_as_uint(Xs[(m0 + qr)     * XS_LD + k0 + qc + 4]);
        unsigned a3 = __float_as_uint(Xs[(m0 + qr + 8) * XS_LD + k0 + qc + 4]);
#pragma unroll
        for (int t = 0; t < 16; t++) {
            unsigned b0 = __float_as_uint(Ws[(k0 + qc)     * WS_LD + t * 8 + qr]);
            unsigned b1 = __float_as_uint(Ws[(k0 + qc + 4) * WS_LD + t * 8 + qr]);
            asm volatile(
                "mma.sync.aligned.m16n8k8.row.col.f32.tf32.tf32.f32 "
                "{%0,%1,%2,%3}, {%4,%5,%6,%7}, {%8,%9}, {%0,%1,%2,%3};"
                : "+f"(acc[t][0]), "+f"(acc[t][1]), "+f"(acc[t][2]), "+f"(acc[t][3])
                : "r"(a0), "r"(a1), "r"(a2), "r"(a3), "r"(b0), "r"(b1));
        }
    }
}

// GEMM -> fp16 output (feeds edge gather). Optional fused norm on input.
template <int NORM, int RES, int STORE>
__global__ __launch_bounds__(256) void gemm_tf32_half_kernel(
    const float* __restrict__ X, const float* __restrict__ resid,
    const float* __restrict__ alpha, const float* __restrict__ gamma,
    const float* __restrict__ beta, const float* __restrict__ W,
    __half* __restrict__ Y, float* __restrict__ Hout, int n) {
    extern __shared__ float sh[];
    float* Xs = sh;
    float* Ws = sh + 128 * XS_LD;
    const int row0 = blockIdx.x * 128;
    load_tiles<NORM, RES, STORE>(X, resid, alpha, gamma, beta, W, Hout, n, row0, Xs, Ws);
    const int warp = threadIdx.x >> 5;
    const int lane = threadIdx.x & 31;
    const int qr = lane >> 2, qc = lane & 3;
    const int m0 = warp * 16;
    float acc[16][4];
    mma_core(Xs, Ws, m0, qr, qc, acc);
    const int r_lo = row0 + m0 + qr;
    const int r_hi = r_lo + 8;
    if (r_lo < n) {
#pragma unroll
        for (int t = 0; t < 16; t++)
            *(__half2*)&Y[(size_t)r_lo * 128 + t * 8 + qc * 2] =
                __floats2half2_rn(acc[t][0], acc[t][1]);
    }
    if (r_hi < n) {
#pragma unroll
        for (int t = 0; t < 16; t++)
            *(__half2*)&Y[(size_t)r_hi * 128 + t * 8 + qc * 2] =
                __floats2half2_rn(acc[t][2], acc[t][3]);
    }
}

// final GEMM (fused norm input) with fused predictor head:
// out[r] = sigmoid( sum_c relu(acc[r][c]+bp1[c]) * Wp2[c] + bp2 )
__global__ __launch_bounds__(256) void gemm_tf32_head_kernel(
    const float* __restrict__ X,
    const float* __restrict__ alpha, const float* __restrict__ gamma,
    const float* __restrict__ beta, const float* __restrict__ W,
    const float* __restrict__ bp1, const float* __restrict__ Wp2,
    const float* __restrict__ bp2, float* __restrict__ out, int n) {
    extern __shared__ float sh[];
    float* Xs = sh;
    float* Ws = sh + 128 * XS_LD;
    const int row0 = blockIdx.x * 128;
    load_tiles<1, 0, 0>(X, nullptr, alpha, gamma, beta, W, nullptr, n, row0, Xs, Ws);
    const int warp = threadIdx.x >> 5;
    const int lane = threadIdx.x & 31;
    const int qr = lane >> 2, qc = lane & 3;
    const int m0 = warp * 16;
    float acc[16][4];
    mma_core(Xs, Ws, m0, qr, qc, acc);
    const int r_lo = row0 + m0 + qr;
    const int r_hi = r_lo + 8;
    float p_lo = 0.f, p_hi = 0.f;
#pragma unroll
    for (int t = 0; t < 16; t++) {
        int c = t * 8 + qc * 2;
        float b0v = bp1[c], b1v = bp1[c + 1];
        float w0v = Wp2[c], w1v = Wp2[c + 1];
        p_lo += fmaxf(acc[t][0] + b0v, 0.f) * w0v + fmaxf(acc[t][1] + b1v, 0.f) * w1v;
        p_hi += fmaxf(acc[t][2] + b0v, 0.f) * w0v + fmaxf(acc[t][3] + b1v, 0.f) * w1v;
    }
    p_lo += __shfl_xor_sync(0xffffffffu, p_lo, 1);
    p_lo += __shfl_xor_sync(0xffffffffu, p_lo, 2);
    p_hi += __shfl_xor_sync(0xffffffffu, p_hi, 1);
    p_hi += __shfl_xor_sync(0xffffffffu, p_hi, 2);
    if (qc == 0) {
        float bb = bp2[0];
        if (r_lo < n) out[r_lo] = 1.f / (1.f + expf(-(p_lo + bb)));
        if (r_hi < n) out[r_hi] = 1.f / (1.f + expf(-(p_hi + bb)));
    }
}

// ---------------- CSR aggregation (fp16 gather, fp32 accumulate) --------------
__global__ void agg_kernel(const __half* __restrict__ T, const float* __restrict__ bias,
                           float* __restrict__ A) {
    int warp = (blockIdx.x * blockDim.x + threadIdx.x) >> 5;
    if (warp >= Nn) return;
    int lane = threadIdx.x & 31;
    int s = d_rowptr[warp], e = d_rowptr[warp + 1];
    float ax = 0.f, ay = 0.f, az = 0.f, aw = 0.f;
    int p = s;
    for (; p + 4 <= e; p += 4) {
        int c0 = d_col[p], c1 = d_col[p + 1], c2 = d_col[p + 2], c3 = d_col[p + 3];
        float w0 = d_w[p], w1 = d_w[p + 1], w2 = d_w[p + 2], w3 = d_w[p + 3];
        uint2 u0 = ((const uint2*)(T + (size_t)c0 * 128))[lane];
        uint2 u1 = ((const uint2*)(T + (size_t)c1 * 128))[lane];
        uint2 u2 = ((const uint2*)(T + (size_t)c2 * 128))[lane];
        uint2 u3 = ((const uint2*)(T + (size_t)c3 * 128))[lane];
        float2 a0 = __half22float2(*(__half2*)&u0.x), b0 = __half22float2(*(__half2*)&u0.y);
        float2 a1 = __half22float2(*(__half2*)&u1.x), b1 = __half22float2(*(__half2*)&u1.y);
        float2 a2 = __half22float2(*(__half2*)&u2.x), b2 = __half22float2(*(__half2*)&u2.y);
        float2 a3 = __half22float2(*(__half2*)&u3.x), b3 = __half22float2(*(__half2*)&u3.y);
        ax += w0 * a0.x + w1 * a1.x + w2 * a2.x + w3 * a3.x;
        ay += w0 * a0.y + w1 * a1.y + w2 * a2.y + w3 * a3.y;
        az += w0 * b0.x + w1 * b1.x + w2 * b2.x + w3 * b3.x;
        aw += w0 * b0.y + w1 * b1.y + w2 * b2.y + w3 * b3.y;
    }
    for (; p < e; p++) {
        int c = d_col[p];
        float w = d_w[p];
        uint2 u = ((const uint2*)(T + (size_t)c * 128))[lane];
        float2 a = __half22float2(*(__half2*)&u.x), b = __half22float2(*(__half2*)&u.y);
        ax += w * a.x; ay += w * a.y; az += w * b.x; aw += w * b.y;
    }
    float ds = d_dis[warp];
    float sl = ds * ds;
    uint2 ut = ((const uint2*)(T + (size_t)warp * 128))[lane];
    float2 ta = __half22float2(*(__half2*)&ut.x), tb = __half22float2(*(__half2*)&ut.y);
    float4 bb = *(const float4*)&bias[lane * 4];
    float4 o;
    o.x = ax + sl * ta.x + bb.x;
    o.y = ay + sl * ta.y + bb.y;
    o.z = az + sl * tb.x + bb.z;
    o.w = aw + sl * tb.y + bb.w;
    *(float4*)&A[(size_t)warp * 128 + lane * 4] = o;
}

// ---------------- GraphNorm: single-pass sum + sumsq reduction ----------------
__global__ void reduce_kernel(const float* __restrict__ A, const float* __restrict__ alpha) {
    int g = blockIdx.x;
    int lane = threadIdx.x & 31;
    int f = blockIdx.y * 32 + lane;
    int sub = threadIdx.x >> 5;  // 0..7
    int s = d_gstart[g], e = d_gstart[g + 1];
    float sum = 0.f, sq = 0.f;
    for (int i = s + sub; i < e; i += 8) {
        float v = A[(size_t)i * 128 + f];
        sum += v; sq += v * v;
    }
    __shared__ float sh1[8][32], sh2[8][32];
    sh1[sub][lane] = sum;
    sh2[sub][lane] = sq;
    __syncthreads();
    if (sub == 0) {
        float t1 = 0.f, t2 = 0.f;
#pragma unroll
        for (int k = 0; k < 8; k++) { t1 += sh1[k][lane]; t2 += sh2[k][lane]; }
        float inv = 1.f / d_gcntf[g];
        float m = t1 * inv;
        float q = t2 * inv;
        float al = alpha[f];
        d_mean[g * 128 + f] = m;
        d_var[g * 128 + f] = q - m * m * al * (2.f - al);
    }
}

// ---------------- host orchestration ----------------
extern "C" void kernel_launch(void* const* d_in, const int* in_sizes, int n_in,
                              void* d_out, int out_size) {
    const float* x   = (const float*)d_in[0];
    const void*  ei  = d_in[1];
    const void*  bt  = d_in[2];
    const float* W1  = (const float*)d_in[3];
    const float* b1  = (const float*)d_in[4];
    const float* a1  = (const float*)d_in[5];
    const float* g1  = (const float*)d_in[6];
    const float* be1 = (const float*)d_in[7];
    const float* Wm  = (const float*)d_in[8];
    const float* bm  = (const float*)d_in[9];
    const float* am  = (const float*)d_in[10];
    const float* gm  = (const float*)d_in[11];
    const float* bem = (const float*)d_in[12];
    const float* WL  = (const float*)d_in[13];
    const float* bL  = (const float*)d_in[14];
    const float* aL  = (const float*)d_in[15];
    const float* gL  = (const float*)d_in[16];
    const float* beL = (const float*)d_in[17];
    const float* Wp1 = (const float*)d_in[18];
    const float* bp1 = (const float*)d_in[19];
    const float* Wp2 = (const float*)d_in[20];
    const float* bp2 = (const float*)d_in[21];
    float* out = (float*)d_out;

    float *HA, *HB, *A;
    __half* Th;
    cudaGetSymbolAddress((void**)&HA, d_HA);
    cudaGetSymbolAddress((void**)&HB, d_HB);
    cudaGetSymbolAddress((void**)&Th, d_Th);
    cudaGetSymbolAddress((void**)&A,  d_A);

    const int smem = (128 * XS_LD + 128 * WS_LD) * (int)sizeof(float);
    cudaFuncSetAttribute(gemm_tf32_half_kernel<0, 0, 0>, cudaFuncAttributeMaxDynamicSharedMemorySize, smem);
    cudaFuncSetAttribute(gemm_tf32_half_kernel<1, 0, 1>, cudaFuncAttributeMaxDynamicSharedMemorySize, smem);
    cudaFuncSetAttribute(gemm_tf32_half_kernel<1, 1, 1>, cudaFuncAttributeMaxDynamicSharedMemorySize, smem);
    cudaFuncSetAttribute(gemm_tf32_half_kernel<1, 1, 0>, cudaFuncAttributeMaxDynamicSharedMemorySize, smem);
    cudaFuncSetAttribute(gemm_tf32_head_kernel, cudaFuncAttributeMaxDynamicSharedMemorySize, smem);

    // ---- preprocessing (4 launches) ----
    zero_detect_kernel<<<NB_SCAN, 256>>>(ei);
    convert_hist_kernel<<<1024, 256>>>(ei, bt);
    scan_fused_kernel<<<NB_SCAN, 256>>>();
    scatter_kernel<<<(Ee + 255) / 256, 256>>>();

    const int gemm_grid = (Nn + 127) / 128;
    const int agg_grid  = (Nn * 32 + 255) / 256;
    dim3 red_grid(NGg, 4);

    // ---- layer 1 GEMM: x @ W1 -> Th ----
    gemm_tf32_half_kernel<0, 0, 0><<<gemm_grid, 256, smem>>>(
        x, nullptr, nullptr, nullptr, nullptr, W1, Th, nullptr, Nn);
    agg_kernel<<<agg_grid, 256>>>(Th, b1, A);
    reduce_kernel<<<red_grid, 256>>>(A, a1);

    // ---- layer 2 GEMM (fused norm of layer 1; h1 -> HB) ----
    gemm_tf32_half_kernel<1, 0, 1><<<gemm_grid, 256, smem>>>(
        A, nullptr, a1, g1, be1, Wm + 0 * 128 * 128, Th, HB, Nn);
    agg_kernel<<<agg_grid, 256>>>(Th, bm + 0 * 128, A);
    reduce_kernel<<<red_grid, 256>>>(A, am + 0 * 128);

    // ---- layer 3 GEMM (fused norm + residual h1; h2 -> HA) ----
    gemm_tf32_half_kernel<1, 1, 1><<<gemm_grid, 256, smem>>>(
        A, HB, am + 0 * 128, gm + 0 * 128, bem + 0 * 128, Wm + 1 * 128 * 128, Th, HA, Nn);
    agg_kernel<<<agg_grid, 256>>>(Th, bm + 1 * 128, A);
    reduce_kernel<<<red_grid, 256>>>(A, am + 1 * 128);

    // ---- layer 4 GEMM (fused norm + residual h2; h3 not stored) ----
    gemm_tf32_half_kernel<1, 1, 0><<<gemm_grid, 256, smem>>>(
        A, HA, am + 1 * 128, gm + 1 * 128, bem + 1 * 128, WL, Th, nullptr, Nn);
    agg_kernel<<<agg_grid, 256>>>(Th, bL, A);
    reduce_kernel<<<red_grid, 256>>>(A, aL);

    // ---- predictor GEMM (fused norm of layer 4 + relu-MLP head) ----
    gemm_tf32_head_kernel<<<gemm_grid, 256, smem>>>(
        A, aL, gL, beL, Wp1, bp1, Wp2, bp2, out, Nn);
}

// round 5
// speedup vs baseline: 1.1001x; 1.1001x over previous
#include <cuda_runtime.h>
#include <cuda_fp16.h>
#include <math.h>

#define Nn 50000
#define Hh 128
#define Ee 800000
#define NGg 64
#define EPSc 1e-5f
#define NB_SCAN 196   // ceil(50000/256)

// ---------------- device scratch (static globals; no allocation) ----------------
__device__ int    g_is64;
__device__ int    d_src[Ee];
__device__ int    d_dst[Ee];
__device__ int    d_batch[Nn];
__device__ int    d_deg[Nn];
__device__ float  d_dis[Nn];
__device__ int    d_rowptr[Nn + 1];
__device__ int    d_cursor[Nn];
__device__ int    d_col[Ee];
__device__ float  d_w[Ee];
__device__ unsigned long long d_scan_state[NB_SCAN];
__device__ unsigned d_ticket;
__device__ int    d_gstart[NGg + 1];
__device__ float  d_gcntf[NGg];
__device__ float  d_mean[NGg * Hh];
__device__ float  d_var[NGg * Hh];
__device__ float  d_HA[(size_t)Nn * Hh];
__device__ float  d_HB[(size_t)Nn * Hh];
__device__ __half d_Th[(size_t)Nn * Hh];
__device__ float  d_A[(size_t)Nn * Hh];

// ---------------- preprocessing ----------------

// zero degree array + scan state + ticket, and detect index dtype
__global__ void zero_detect_kernel(const void* ei) {
    int i = blockIdx.x * blockDim.x + threadIdx.x;
    if (i < Nn) d_deg[i] = 0;
    if (i < NB_SCAN) d_scan_state[i] = 0ull;
    if (i == 0) {
        d_ticket = 0u;
        const long long* p = (const long long*)ei;
        int ok = 1;
        for (int k = 0; k < 64; k++) {
            long long v = p[k];
            if (v < 0 || v >= (long long)Nn) ok = 0;
        }
        g_is64 = ok;
    }
}

// fused: convert edge_index + batch to int32, histogram dst degrees
__global__ void convert_hist_kernel(const void* ei, const void* bt) {
    int is64 = g_is64;
    int stride = gridDim.x * blockDim.x;
    for (int i = blockIdx.x * blockDim.x + threadIdx.x; i < 2 * Ee; i += stride) {
        int v = is64 ? (int)((const long long*)ei)[i] : ((const int*)ei)[i];
        if (i < Ee) d_src[i] = v;
        else { d_dst[i - Ee] = v; atomicAdd(&d_deg[v], 1); }
    }
    for (int i = blockIdx.x * blockDim.x + threadIdx.x; i < Nn; i += stride) {
        int v = is64 ? (int)((const long long*)bt)[i] : ((const int*)bt)[i];
        d_batch[i] = v;
    }
}

// single-kernel decoupled-lookback scan of d_deg -> rowptr/cursor/dis,
// plus per-graph ranges (block 0).
__global__ void scan_fused_kernel() {
    __shared__ unsigned sbid;
    __shared__ int s_excl;
    __shared__ int sh[256];
    if (threadIdx.x == 0) sbid = atomicAdd(&d_ticket, 1u);
    __syncthreads();
    int b = (int)sbid;
    int idx = b * 256 + threadIdx.x;
    int deg = (idx < Nn) ? d_deg[idx] : 0;
    sh[threadIdx.x] = deg;
    __syncthreads();
    for (int off = 1; off < 256; off <<= 1) {
        int u = 0;
        if (threadIdx.x >= off) u = sh[threadIdx.x - off];
        __syncthreads();
        if (threadIdx.x >= off) sh[threadIdx.x] += u;
        __syncthreads();
    }
    int incl = sh[threadIdx.x];
    int aggr = sh[255];
    if (threadIdx.x == 0) {
        if (b == 0) {
            atomicExch(&d_scan_state[0], (2ull << 32) | (unsigned)aggr);
            s_excl = 0;
        } else {
            atomicExch(&d_scan_state[b], (1ull << 32) | (unsigned)aggr);
            int excl = 0;
            int j = b - 1;
            while (true) {
                unsigned long long st;
                do { st = atomicAdd(&d_scan_state[j], 0ull); } while ((st >> 32) == 0ull);
                excl += (int)(unsigned)st;
                if ((st >> 32) == 2ull) break;
                j--;
            }
            atomicExch(&d_scan_state[b], (2ull << 32) | (unsigned)(excl + aggr));
            s_excl = excl;
        }
    }
    __syncthreads();
    int excl = s_excl;
    if (idx < Nn) {
        d_rowptr[idx + 1] = excl + incl;
        if (idx == 0) d_rowptr[0] = 0;
        d_cursor[idx] = excl + incl - deg;
        d_dis[idx] = rsqrtf((float)deg + 1.0f);
    }
    // block 0 additionally computes per-graph node ranges (batch is sorted)
    if (b == 0) {
        int t = threadIdx.x;
        if (t <= NGg) {
            int lo = 0, hi = Nn;
            while (lo < hi) {
                int mid = (lo + hi) >> 1;
                if (d_batch[mid] < t) lo = mid + 1; else hi = mid;
            }
            d_gstart[t] = lo;
        }
        __syncthreads();
        if (t < NGg) {
            int c = d_gstart[t + 1] - d_gstart[t];
            d_gcntf[t] = (c > 0) ? (float)c : 1.0f;
        }
    }
}

__global__ void scatter_kernel() {
    int i = blockIdx.x * blockDim.x + threadIdx.x;
    if (i >= Ee) return;
    int s = d_src[i], dd = d_dst[i];
    int pos = atomicAdd(&d_cursor[dd], 1);
    d_col[pos] = s;
    d_w[pos] = d_dis[s] * d_dis[dd];
}

// ---------------- tf32 tensor-core GEMM ----------------
#define XS_LD 132
#define WS_LD 136

__device__ __forceinline__ unsigned f2tf32(float v) {
    unsigned o;
    asm("cvt.rna.tf32.f32 %0, %1;" : "=r"(o) : "f"(v));
    return o;
}

#define TF32_GEMM_CORE()                                                          \
    extern __shared__ float sh[];                                                 \
    float* Xs = sh;                                                               \
    float* Ws = sh + 128 * XS_LD;                                                 \
    const int tid = threadIdx.x;                                                  \
    const int row0 = blockIdx.x * 128;                                            \
    _Pragma("unroll")                                                             \
    for (int i = 0; i < 16; i++) {                                                \
        int idx = i * 256 + tid;                                                  \
        int r = idx >> 5;                                                         \
        int c = (idx & 31) * 4;                                                   \
        float4 wv = *(const float4*)&W[r * 128 + c];                              \
        Ws[r * WS_LD + c + 0] = __uint_as_float(f2tf32(wv.x));                    \
        Ws[r * WS_LD + c + 1] = __uint_as_float(f2tf32(wv.y));                    \
        Ws[r * WS_LD + c + 2] = __uint_as_float(f2tf32(wv.z));                    \
        Ws[r * WS_LD + c + 3] = __uint_as_float(f2tf32(wv.w));                    \
        float4 xv = make_float4(0.f, 0.f, 0.f, 0.f);                              \
        if (row0 + r < n) xv = *(const float4*)&X[(size_t)(row0 + r) * 128 + c];  \
        Xs[r * XS_LD + c + 0] = __uint_as_float(f2tf32(xv.x));                    \
        Xs[r * XS_LD + c + 1] = __uint_as_float(f2tf32(xv.y));                    \
        Xs[r * XS_LD + c + 2] = __uint_as_float(f2tf32(xv.z));                    \
        Xs[r * XS_LD + c + 3] = __uint_as_float(f2tf32(xv.w));                    \
    }                                                                             \
    __syncthreads();                                                              \
    const int warp = tid >> 5;                                                    \
    const int lane = tid & 31;                                                    \
    const int qr = lane >> 2;                                                     \
    const int qc = lane & 3;                                                      \
    const int m0 = warp * 16;                                                     \
    float acc[16][4];                                                             \
    _Pragma("unroll")                                                             \
    for (int t = 0; t < 16; t++) {                                                \
        acc[t][0] = 0.f; acc[t][1] = 0.f; acc[t][2] = 0.f; acc[t][3] = 0.f;       \
    }                                                                             \
    _Pragma("unroll 4")                                                           \
    for (int k0 = 0; k0 < 128; k0 += 8) {                                         \
        unsigned a0 = __float_as_uint(Xs[(m0 + qr)     * XS_LD + k0 + qc]);       \
        unsigned a1 = __float_as_uint(Xs[(m0 + qr + 8) * XS_LD + k0 + qc]);       \
        unsigned a2 = __float_as_uint(Xs[(m0 + qr)     * XS_LD + k0 + qc + 4]);   \
        unsigned a3 = __float_as_uint(Xs[(m0 + qr + 8) * XS_LD + k0 + qc + 4]);   \
        _Pragma("unroll")                                                         \
        for (int t = 0; t < 16; t++) {                                            \
            unsigned b0 = __float_as_uint(Ws[(k0 + qc)     * WS_LD + t * 8 + qr]);\
            unsigned b1 = __float_as_uint(Ws[(k0 + qc + 4) * WS_LD + t * 8 + qr]);\
            asm volatile(                                                         \
                "mma.sync.aligned.m16n8k8.row.col.f32.tf32.tf32.f32 "             \
                "{%0,%1,%2,%3}, {%4,%5,%6,%7}, {%8,%9}, {%0,%1,%2,%3};"           \
                : "+f"(acc[t][0]), "+f"(acc[t][1]),                               \
                  "+f"(acc[t][2]), "+f"(acc[t][3])                                \
                : "r"(a0), "r"(a1), "r"(a2), "r"(a3), "r"(b0), "r"(b1));          \
        }                                                                         \
    }                                                                             \
    const int r_lo = row0 + m0 + qr;                                              \
    const int r_hi = r_lo + 8;

// fp16-output GEMM (feeds edge gather)
__global__ __launch_bounds__(256) void gemm_tf32_half_kernel(
    const float* __restrict__ X, const float* __restrict__ W,
    __half* __restrict__ Y, int n) {
    TF32_GEMM_CORE()
    if (r_lo < n) {
#pragma unroll
        for (int t = 0; t < 16; t++)
            *(__half2*)&Y[(size_t)r_lo * 128 + t * 8 + qc * 2] =
                __floats2half2_rn(acc[t][0], acc[t][1]);
    }
    if (r_hi < n) {
#pragma unroll
        for (int t = 0; t < 16; t++)
            *(__half2*)&Y[(size_t)r_hi * 128 + t * 8 + qc * 2] =
                __floats2half2_rn(acc[t][2], acc[t][3]);
    }
}

// final GEMM with fused predictor head:
// out[r] = sigmoid( sum_c relu(acc[r][c]+bp1[c]) * Wp2[c] + bp2 )
__global__ __launch_bounds__(256) void gemm_tf32_head_kernel(
    const float* __restrict__ X, const float* __restrict__ W,
    const float* __restrict__ bp1, const float* __restrict__ Wp2,
    const float* __restrict__ bp2, float* __restrict__ out, int n) {
    TF32_GEMM_CORE()
    float p_lo = 0.f, p_hi = 0.f;
#pragma unroll
    for (int t = 0; t < 16; t++) {
        int c = t * 8 + qc * 2;
        float b0v = bp1[c], b1v = bp1[c + 1];
        float w0v = Wp2[c], w1v = Wp2[c + 1];
        p_lo += fmaxf(acc[t][0] + b0v, 0.f) * w0v + fmaxf(acc[t][1] + b1v, 0.f) * w1v;
        p_hi += fmaxf(acc[t][2] + b0v, 0.f) * w0v + fmaxf(acc[t][3] + b1v, 0.f) * w1v;
    }
    p_lo += __shfl_xor_sync(0xffffffffu, p_lo, 1);
    p_lo += __shfl_xor_sync(0xffffffffu, p_lo, 2);
    p_hi += __shfl_xor_sync(0xffffffffu, p_hi, 1);
    p_hi += __shfl_xor_sync(0xffffffffu, p_hi, 2);
    if (qc == 0) {
        float bb = bp2[0];
        if (r_lo < n) out[r_lo] = 1.f / (1.f + expf(-(p_lo + bb)));
        if (r_hi < n) out[r_hi] = 1.f / (1.f + expf(-(p_hi + bb)));
    }
}

// ---------------- CSR aggregation (fp16 gather, fp32 accumulate) --------------
__global__ void agg_kernel(const __half* __restrict__ T, const float* __restrict__ bias,
                           float* __restrict__ A) {
    int warp = (blockIdx.x * blockDim.x + threadIdx.x) >> 5;
    if (warp >= Nn) return;
    int lane = threadIdx.x & 31;
    int s = d_rowptr[warp], e = d_rowptr[warp + 1];
    float ax = 0.f, ay = 0.f, az = 0.f, aw = 0.f;
    int p = s;
    for (; p + 4 <= e; p += 4) {
        int c0 = d_col[p], c1 = d_col[p + 1], c2 = d_col[p + 2], c3 = d_col[p + 3];
        float w0 = d_w[p], w1 = d_w[p + 1], w2 = d_w[p + 2], w3 = d_w[p + 3];
        uint2 u0 = ((const uint2*)(T + (size_t)c0 * 128))[lane];
        uint2 u1 = ((const uint2*)(T + (size_t)c1 * 128))[lane];
        uint2 u2 = ((const uint2*)(T + (size_t)c2 * 128))[lane];
        uint2 u3 = ((const uint2*)(T + (size_t)c3 * 128))[lane];
        float2 a0 = __half22float2(*(__half2*)&u0.x), b0 = __half22float2(*(__half2*)&u0.y);
        float2 a1 = __half22float2(*(__half2*)&u1.x), b1 = __half22float2(*(__half2*)&u1.y);
        float2 a2 = __half22float2(*(__half2*)&u2.x), b2 = __half22float2(*(__half2*)&u2.y);
        float2 a3 = __half22float2(*(__half2*)&u3.x), b3 = __half22float2(*(__half2*)&u3.y);
        ax += w0 * a0.x + w1 * a1.x + w2 * a2.x + w3 * a3.x;
        ay += w0 * a0.y + w1 * a1.y + w2 * a2.y + w3 * a3.y;
        az += w0 * b0.x + w1 * b1.x + w2 * b2.x + w3 * b3.x;
        aw += w0 * b0.y + w1 * b1.y + w2 * b2.y + w3 * b3.y;
    }
    for (; p < e; p++) {
        int c = d_col[p];
        float w = d_w[p];
        uint2 u = ((const uint2*)(T + (size_t)c * 128))[lane];
        float2 a = __half22float2(*(__half2*)&u.x), b = __half22float2(*(__half2*)&u.y);
        ax += w * a.x; ay += w * a.y; az += w * b.x; aw += w * b.y;
    }
    float ds = d_dis[warp];
    float sl = ds * ds;
    uint2 ut = ((const uint2*)(T + (size_t)warp * 128))[lane];
    float2 ta = __half22float2(*(__half2*)&ut.x), tb = __half22float2(*(__half2*)&ut.y);
    float4 bb = *(const float4*)&bias[lane * 4];
    float4 o;
    o.x = ax + sl * ta.x + bb.x;
    o.y = ay + sl * ta.y + bb.y;
    o.z = az + sl * tb.x + bb.z;
    o.w = aw + sl * tb.y + bb.w;
    *(float4*)&A[(size_t)warp * 128 + lane * 4] = o;
}

// ---------------- GraphNorm: single-pass sum + sumsq reduction ----------------
__global__ void reduce_kernel(const float* __restrict__ A, const float* __restrict__ alpha) {
    int g = blockIdx.x;
    int lane = threadIdx.x & 31;
    int f = blockIdx.y * 32 + lane;
    int sub = threadIdx.x >> 5;  // 0..7
    int s = d_gstart[g], e = d_gstart[g + 1];
    float sum = 0.f, sq = 0.f;
    for (int i = s + sub; i < e; i += 8) {
        float v = A[(size_t)i * 128 + f];
        sum += v; sq += v * v;
    }
    __shared__ float sh1[8][32], sh2[8][32];
    sh1[sub][lane] = sum;
    sh2[sub][lane] = sq;
    __syncthreads();
    if (sub == 0) {
        float t1 = 0.f, t2 = 0.f;
#pragma unroll
        for (int k = 0; k < 8; k++) { t1 += sh1[k][lane]; t2 += sh2[k][lane]; }
        float inv = 1.f / d_gcntf[g];
        float m = t1 * inv;
        float q = t2 * inv;
        float al = alpha[f];
        d_mean[g * 128 + f] = m;
        d_var[g * 128 + f] = q - m * m * al * (2.f - al);
    }
}

// out = [in +] relu((A - alpha*mean) * rsqrt(var+eps) * gamma + beta)
template <int RES>
__global__ void final_kernel(const float* __restrict__ A, const float* __restrict__ in,
                             const float* __restrict__ alpha, const float* __restrict__ gamma,
                             const float* __restrict__ beta, float* __restrict__ out) {
    int idx = blockIdx.x * blockDim.x + threadIdx.x;  // over N*32 float4s
    if (idx >= Nn * 32) return;
    int node = idx >> 5;
    int q = idx & 31;
    int g = d_batch[node];
    float4 a = ((const float4*)A)[idx];
    float4 m = *(const float4*)&d_mean[g * 128 + q * 4];
    float4 vv = *(const float4*)&d_var[g * 128 + q * 4];
    float4 al = *(const float4*)&alpha[q * 4];
    float4 ga = *(const float4*)&gamma[q * 4];
    float4 be = *(const float4*)&beta[q * 4];
    float4 o;
    o.x = fmaxf((a.x - al.x * m.x) * rsqrtf(vv.x + EPSc) * ga.x + be.x, 0.f);
    o.y = fmaxf((a.y - al.y * m.y) * rsqrtf(vv.y + EPSc) * ga.y + be.y, 0.f);
    o.z = fmaxf((a.z - al.z * m.z) * rsqrtf(vv.z + EPSc) * ga.z + be.z, 0.f);
    o.w = fmaxf((a.w - al.w * m.w) * rsqrtf(vv.w + EPSc) * ga.w + be.w, 0.f);
    if (RES) {
        float4 r = ((const float4*)in)[idx];
        o.x += r.x; o.y += r.y; o.z += r.z; o.w += r.w;
    }
    ((float4*)out)[idx] = o;
}

// ---------------- host orchestration ----------------
extern "C" void kernel_launch(void* const* d_in, const int* in_sizes, int n_in,
                              void* d_out, int out_size) {
    const float* x   = (const float*)d_in[0];
    const void*  ei  = d_in[1];
    const void*  bt  = d_in[2];
    const float* W1  = (const float*)d_in[3];
    const float* b1  = (const float*)d_in[4];
    const float* a1  = (const float*)d_in[5];
    const float* g1  = (const float*)d_in[6];
    const float* be1 = (const float*)d_in[7];
    const float* Wm  = (const float*)d_in[8];
    const float* bm  = (const float*)d_in[9];
    const float* am  = (const float*)d_in[10];
    const float* gm  = (const float*)d_in[11];
    const float* bem = (const float*)d_in[12];
    const float* WL  = (const float*)d_in[13];
    const float* bL  = (const float*)d_in[14];
    const float* aL  = (const float*)d_in[15];
    const float* gL  = (const float*)d_in[16];
    const float* beL = (const float*)d_in[17];
    const float* Wp1 = (const float*)d_in[18];
    const float* bp1 = (const float*)d_in[19];
    const float* Wp2 = (const float*)d_in[20];
    const float* bp2 = (const float*)d_in[21];
    float* out = (float*)d_out;

    float *HA, *HB, *A;
    __half* Th;
    cudaGetSymbolAddress((void**)&HA, d_HA);
    cudaGetSymbolAddress((void**)&HB, d_HB);
    cudaGetSymbolAddress((void**)&Th, d_Th);
    cudaGetSymbolAddress((void**)&A,  d_A);

    const int smem = (128 * XS_LD + 128 * WS_LD) * (int)sizeof(float);
    cudaFuncSetAttribute(gemm_tf32_half_kernel, cudaFuncAttributeMaxDynamicSharedMemorySize, smem);
    cudaFuncSetAttribute(gemm_tf32_head_kernel, cudaFuncAttributeMaxDynamicSharedMemorySize, smem);

    // ---- preprocessing (4 launches) ----
    zero_detect_kernel<<<NB_SCAN, 256>>>(ei);
    convert_hist_kernel<<<1024, 256>>>(ei, bt);
    scan_fused_kernel<<<NB_SCAN, 256>>>();
    scatter_kernel<<<(Ee + 255) / 256, 256>>>();

    const int gemm_grid = (Nn + 127) / 128;
    const int agg_grid  = (Nn * 32 + 255) / 256;
    const int elem_grid = (Nn * 32 + 511) / 512;
    dim3 red_grid(NGg, 4);

    // ---- layer 1: x -> HB ----
    gemm_tf32_half_kernel<<<gemm_grid, 256, smem>>>(x, W1, Th, Nn);
    agg_kernel<<<agg_grid, 256>>>(Th, b1, A);
    reduce_kernel<<<red_grid, 256>>>(A, a1);
    final_kernel<0><<<elem_grid, 512>>>(A, nullptr, a1, g1, be1, HB);

    // ---- mid layer 0 (residual): HB -> HA ----
    gemm_tf32_half_kernel<<<gemm_grid, 256, smem>>>(HB, Wm + 0 * 128 * 128, Th, Nn);
    agg_kernel<<<agg_grid, 256>>>(Th, bm + 0 * 128, A);
    reduce_kernel<<<red_grid, 256>>>(A, am + 0 * 128);
    final_kernel<1><<<elem_grid, 512>>>(A, HB, am + 0 * 128, gm + 0 * 128, bem + 0 * 128, HA);

    // ---- mid layer 1 (residual): HA -> HB ----
    gemm_tf32_half_kernel<<<gemm_grid, 256, smem>>>(HA, Wm + 1 * 128 * 128, Th, Nn);
    agg_kernel<<<agg_grid, 256>>>(Th, bm + 1 * 128, A);
    reduce_kernel<<<red_grid, 256>>>(A, am + 1 * 128);
    final_kernel<1><<<elem_grid, 512>>>(A, HA, am + 1 * 128, gm + 1 * 128, bem + 1 * 128, HB);

    // ---- last layer: HB -> HA ----
    gemm_tf32_half_kernel<<<gemm_grid, 256, smem>>>(HB, WL, Th, Nn);
    agg_kernel<<<agg_grid, 256>>>(Th, bL, A);
    reduce_kernel<<<red_grid, 256>>>(A, aL);
    final_kernel<0><<<elem_grid, 512>>>(A, nullptr, aL, gL, beL, HA);

    // ---- predictor: HA -> out (tf32 GEMM with fused relu-MLP head) ----
    gemm_tf32_head_kernel<<<gemm_grid, 256, smem>>>(HA, Wp1, bp1, Wp2, bp2, out, Nn);
}

// round 6
// speedup vs baseline: 1.3253x; 1.2047x over previous
#include <cuda_runtime.h>
#include <cuda_fp16.h>
#include <math.h>

#define Nn 50000
#define Hh 128
#define Ee 800000
#define NGg 64
#define EPSc 1e-5f
#define NB_SCAN 196   // ceil(50000/256)

// ---------------- device scratch (static globals; no allocation) ----------------
__device__ int    g_is64;
__device__ int    d_batch[Nn];
__device__ int    d_deg[Nn];
__device__ float  d_dis[Nn];
__device__ int    d_rowptr[Nn + 1];
__device__ int    d_cursor[Nn];
__device__ int2   d_colw[Ee];
__device__ unsigned long long d_scan_state[NB_SCAN];
__device__ unsigned d_ticket;
__device__ int    d_gstart[NGg + 1];
__device__ float  d_gcntf[NGg];
__device__ float  d_gsum[4 * NGg * Hh];
__device__ float  d_gsq[4 * NGg * Hh];
__device__ float  d_HA[(size_t)Nn * Hh];
__device__ float  d_HB[(size_t)Nn * Hh];
__device__ __half d_Th[(size_t)Nn * Hh];
__device__ float  d_A[(size_t)Nn * Hh];

// ---------------- preprocessing ----------------

// zero degree array + scan state + per-layer accumulators + ticket; detect dtype
__global__ void zero_detect_kernel(const void* ei) {
    int i = blockIdx.x * blockDim.x + threadIdx.x;
    int total = gridDim.x * blockDim.x;
    if (i < Nn) d_deg[i] = 0;
    if (i < NB_SCAN) d_scan_state[i] = 0ull;
    for (int j = i; j < 4 * NGg * Hh; j += total) { d_gsum[j] = 0.f; d_gsq[j] = 0.f; }
    if (i == 0) {
        d_ticket = 0u;
        const long long* p = (const long long*)ei;
        int ok = 1;
        for (int k = 0; k < 64; k++) {
            long long v = p[k];
            if (v < 0 || v >= (long long)Nn) ok = 0;
        }
        g_is64 = ok;
    }
}

// convert batch to int32, histogram dst degrees (reads dst half of edge_index only)
__global__ void convert_hist_kernel(const void* ei, const void* bt) {
    int is64 = g_is64;
    int stride = gridDim.x * blockDim.x;
    for (int i = blockIdx.x * blockDim.x + threadIdx.x; i < Ee; i += stride) {
        int v = is64 ? (int)((const long long*)ei)[Ee + i] : ((const int*)ei)[Ee + i];
        atomicAdd(&d_deg[v], 1);
    }
    for (int i = blockIdx.x * blockDim.x + threadIdx.x; i < Nn; i += stride) {
        int v = is64 ? (int)((const long long*)bt)[i] : ((const int*)bt)[i];
        d_batch[i] = v;
    }
}

// single-kernel decoupled-lookback scan of d_deg -> rowptr/cursor/dis,
// plus per-graph ranges (block 0).
__global__ void scan_fused_kernel() {
    __shared__ unsigned sbid;
    __shared__ int s_excl;
    __shared__ int sh[256];
    if (threadIdx.x == 0) sbid = atomicAdd(&d_ticket, 1u);
    __syncthreads();
    int b = (int)sbid;
    int idx = b * 256 + threadIdx.x;
    int deg = (idx < Nn) ? d_deg[idx] : 0;
    sh[threadIdx.x] = deg;
    __syncthreads();
    for (int off = 1; off < 256; off <<= 1) {
        int u = 0;
        if (threadIdx.x >= off) u = sh[threadIdx.x - off];
        __syncthreads();
        if (threadIdx.x >= off) sh[threadIdx.x] += u;
        __syncthreads();
    }
    int incl = sh[threadIdx.x];
    int aggr = sh[255];
    if (threadIdx.x == 0) {
        if (b == 0) {
            atomicExch(&d_scan_state[0], (2ull << 32) | (unsigned)aggr);
            s_excl = 0;
        } else {
            atomicExch(&d_scan_state[b], (1ull << 32) | (unsigned)aggr);
            int excl = 0;
            int j = b - 1;
            while (true) {
                unsigned long long st;
                do { st = atomicAdd(&d_scan_state[j], 0ull); } while ((st >> 32) == 0ull);
                excl += (int)(unsigned)st;
                if ((st >> 32) == 2ull) break;
                j--;
            }
            atomicExch(&d_scan_state[b], (2ull << 32) | (unsigned)(excl + aggr));
            s_excl = excl;
        }
    }
    __syncthreads();
    int excl = s_excl;
    if (idx < Nn) {
        d_rowptr[idx + 1] = excl + incl;
        if (idx == 0) d_rowptr[0] = 0;
        d_cursor[idx] = excl + incl - deg;
        d_dis[idx] = rsqrtf((float)deg + 1.0f);
    }
    if (b == 0) {
        int t = threadIdx.x;
        if (t <= NGg) {
            int lo = 0, hi = Nn;
            while (lo < hi) {
                int mid = (lo + hi) >> 1;
                if (d_batch[mid] < t) lo = mid + 1; else hi = mid;
            }
            d_gstart[t] = lo;
        }
        __syncthreads();
        if (t < NGg) {
            int c = d_gstart[t + 1] - d_gstart[t];
            d_gcntf[t] = (c > 0) ? (float)c : 1.0f;
        }
    }
}

// scatter edges into CSR; reads edge_index directly (no staging)
__global__ void scatter_kernel(const void* ei) {
    int i = blockIdx.x * blockDim.x + threadIdx.x;
    if (i >= Ee) return;
    int s, dd;
    if (g_is64) {
        s  = (int)((const long long*)ei)[i];
        dd = (int)((const long long*)ei)[Ee + i];
    } else {
        s  = ((const int*)ei)[i];
        dd = ((const int*)ei)[Ee + i];
    }
    int pos = atomicAdd(&d_cursor[dd], 1);
    d_colw[pos] = make_int2(s, __float_as_int(d_dis[s] * d_dis[dd]));
}

// ---------------- tf32 tensor-core GEMM ----------------
#define XS_LD 132
#define WS_LD 136

__device__ __forceinline__ unsigned f2tf32(float v) {
    unsigned o;
    asm("cvt.rna.tf32.f32 %0, %1;" : "=r"(o) : "f"(v));
    return o;
}

#define TF32_GEMM_CORE()                                                          \
    extern __shared__ float sh[];                                                 \
    float* Xs = sh;                                                               \
    float* Ws = sh + 128 * XS_LD;                                                 \
    const int tid = threadIdx.x;                                                  \
    const int row0 = blockIdx.x * 128;                                            \
    _Pragma("unroll")                                                             \
    for (int i = 0; i < 16; i++) {                                                \
        int idx = i * 256 + tid;                                                  \
        int r = idx >> 5;                                                         \
        int c = (idx & 31) * 4;                                                   \
        float4 wv = *(const float4*)&W[r * 128 + c];                              \
        Ws[r * WS_LD + c + 0] = __uint_as_float(f2tf32(wv.x));                    \
        Ws[r * WS_LD + c + 1] = __uint_as_float(f2tf32(wv.y));                    \
        Ws[r * WS_LD + c + 2] = __uint_as_float(f2tf32(wv.z));                    \
        Ws[r * WS_LD + c + 3] = __uint_as_float(f2tf32(wv.w));                    \
        float4 xv = make_float4(0.f, 0.f, 0.f, 0.f);                              \
        if (row0 + r < n) xv = *(const float4*)&X[(size_t)(row0 + r) * 128 + c];  \
        Xs[r * XS_LD + c + 0] = __uint_as_float(f2tf32(xv.x));                    \
        Xs[r * XS_LD + c + 1] = __uint_as_float(f2tf32(xv.y));                    \
        Xs[r * XS_LD + c + 2] = __uint_as_float(f2tf32(xv.z));                    \
        Xs[r * XS_LD + c + 3] = __uint_as_float(f2tf32(xv.w));                    \
    }                                                                             \
    __syncthreads();                                                              \
    const int warp = tid >> 5;                                                    \
    const int lane = tid & 31;                                                    \
    const int qr = lane >> 2;                                                     \
    const int qc = lane & 3;                                                      \
    const int m0 = warp * 16;                                                     \
    float acc[16][4];                                                             \
    _Pragma("unroll")                                                             \
    for (int t = 0; t < 16; t++) {                                                \
        acc[t][0] = 0.f; acc[t][1] = 0.f; acc[t][2] = 0.f; acc[t][3] = 0.f;       \
    }                                                                             \
    _Pragma("unroll 4")                                                           \
    for (int k0 = 0; k0 < 128; k0 += 8) {                                         \
        unsigned a0 = __float_as_uint(Xs[(m0 + qr)     * XS_LD + k0 + qc]);       \
        unsigned a1 = __float_as_uint(Xs[(m0 + qr + 8) * XS_LD + k0 + qc]);       \
        unsigned a2 = __float_as_uint(Xs[(m0 + qr)     * XS_LD + k0 + qc + 4]);   \
        unsigned a3 = __float_as_uint(Xs[(m0 + qr + 8) * XS_LD + k0 + qc + 4]);   \
        _Pragma("unroll")                                                         \
        for (int t = 0; t < 16; t++) {                                            \
            unsigned b0 = __float_as_uint(Ws[(k0 + qc)     * WS_LD + t * 8 + qr]);\
            unsigned b1 = __float_as_uint(Ws[(k0 + qc + 4) * WS_LD + t * 8 + qr]);\
            asm volatile(                                                         \
                "mma.sync.aligned.m16n8k8.row.col.f32.tf32.tf32.f32 "             \
                "{%0,%1,%2,%3}, {%4,%5,%6,%7}, {%8,%9}, {%0,%1,%2,%3};"           \
                : "+f"(acc[t][0]), "+f"(acc[t][1]),                               \
                  "+f"(acc[t][2]), "+f"(acc[t][3])                                \
                : "r"(a0), "r"(a1), "r"(a2), "r"(a3), "r"(b0), "r"(b1));          \
        }                                                                         \
    }                                                                             \
    const int r_lo = row0 + m0 + qr;                                              \
    const int r_hi = r_lo + 8;

// fp16-output GEMM (feeds edge gather)
__global__ __launch_bounds__(256) void gemm_tf32_half_kernel(
    const float* __restrict__ X, const float* __restrict__ W,
    __half* __restrict__ Y, int n) {
    TF32_GEMM_CORE()
    if (r_lo < n) {
#pragma unroll
        for (int t = 0; t < 16; t++)
            *(__half2*)&Y[(size_t)r_lo * 128 + t * 8 + qc * 2] =
                __floats2half2_rn(acc[t][0], acc[t][1]);
    }
    if (r_hi < n) {
#pragma unroll
        for (int t = 0; t < 16; t++)
            *(__half2*)&Y[(size_t)r_hi * 128 + t * 8 + qc * 2] =
                __floats2half2_rn(acc[t][2], acc[t][3]);
    }
}

// final GEMM with fused predictor head:
// out[r] = sigmoid( sum_c relu(acc[r][c]+bp1[c]) * Wp2[c] + bp2 )
__global__ __launch_bounds__(256) void gemm_tf32_head_kernel(
    const float* __restrict__ X, const float* __restrict__ W,
    const float* __restrict__ bp1, const float* __restrict__ Wp2,
    const float* __restrict__ bp2, float* __restrict__ out, int n) {
    TF32_GEMM_CORE()
    float p_lo = 0.f, p_hi = 0.f;
#pragma unroll
    for (int t = 0; t < 16; t++) {
        int c = t * 8 + qc * 2;
        float b0v = bp1[c], b1v = bp1[c + 1];
        float w0v = Wp2[c], w1v = Wp2[c + 1];
        p_lo += fmaxf(acc[t][0] + b0v, 0.f) * w0v + fmaxf(acc[t][1] + b1v, 0.f) * w1v;
        p_hi += fmaxf(acc[t][2] + b0v, 0.f) * w0v + fmaxf(acc[t][3] + b1v, 0.f) * w1v;
    }
    p_lo += __shfl_xor_sync(0xffffffffu, p_lo, 1);
    p_lo += __shfl_xor_sync(0xffffffffu, p_lo, 2);
    p_hi += __shfl_xor_sync(0xffffffffu, p_hi, 1);
    p_hi += __shfl_xor_sync(0xffffffffu, p_hi, 2);
    if (qc == 0) {
        float bb = bp2[0];
        if (r_lo < n) out[r_lo] = 1.f / (1.f + expf(-(p_lo + bb)));
        if (r_hi < n) out[r_hi] = 1.f / (1.f + expf(-(p_hi + bb)));
    }
}

// ---------------- CSR aggregation + fused per-graph sum/sumsq -----------------
// grid = 6250 blocks x 256 threads; warp w of block b handles node b*8+w (exact).
__global__ void agg_kernel(const __half* __restrict__ T, const float* __restrict__ bias,
                           float* __restrict__ A,
                           float* __restrict__ gsum, float* __restrict__ gsq) {
    __shared__ __align__(16) float s_red[2][8][132];
    __shared__ int s_same, s_g;
    int tid = threadIdx.x;
    int wid = tid >> 5;
    int lane = tid & 31;
    int node = blockIdx.x * 8 + wid;
    if (tid == 0) {
        int g0 = d_batch[blockIdx.x * 8];
        int g7 = d_batch[blockIdx.x * 8 + 7];
        s_same = (g0 == g7);
        s_g = g0;
    }
    int s = d_rowptr[node], e = d_rowptr[node + 1];
    float ax = 0.f, ay = 0.f, az = 0.f, aw = 0.f;
    int p = s;
    for (; p + 4 <= e; p += 4) {
        int2 e0 = d_colw[p], e1 = d_colw[p + 1], e2 = d_colw[p + 2], e3 = d_colw[p + 3];
        float w0 = __int_as_float(e0.y), w1 = __int_as_float(e1.y);
        float w2 = __int_as_float(e2.y), w3 = __int_as_float(e3.y);
        uint2 u0 = ((const uint2*)(T + (size_t)e0.x * 128))[lane];
        uint2 u1 = ((const uint2*)(T + (size_t)e1.x * 128))[lane];
        uint2 u2 = ((const uint2*)(T + (size_t)e2.x * 128))[lane];
        uint2 u3 = ((const uint2*)(T + (size_t)e3.x * 128))[lane];
        float2 a0 = __half22float2(*(__half2*)&u0.x), b0 = __half22float2(*(__half2*)&u0.y);
        float2 a1 = __half22float2(*(__half2*)&u1.x), b1 = __half22float2(*(__half2*)&u1.y);
        float2 a2 = __half22float2(*(__half2*)&u2.x), b2 = __half22float2(*(__half2*)&u2.y);
        float2 a3 = __half22float2(*(__half2*)&u3.x), b3 = __half22float2(*(__half2*)&u3.y);
        ax += w0 * a0.x + w1 * a1.x + w2 * a2.x + w3 * a3.x;
        ay += w0 * a0.y + w1 * a1.y + w2 * a2.y + w3 * a3.y;
        az += w0 * b0.x + w1 * b1.x + w2 * b2.x + w3 * b3.x;
        aw += w0 * b0.y + w1 * b1.y + w2 * b2.y + w3 * b3.y;
    }
    for (; p < e; p++) {
        int2 ec = d_colw[p];
        float w = __int_as_float(ec.y);
        uint2 u = ((const uint2*)(T + (size_t)ec.x * 128))[lane];
        float2 a = __half22float2(*(__half2*)&u.x), b = __half22float2(*(__half2*)&u.y);
        ax += w * a.x; ay += w * a.y; az += w * b.x; aw += w * b.y;
    }
    float ds = d_dis[node];
    float sl = ds * ds;
    uint2 ut = ((const uint2*)(T + (size_t)node * 128))[lane];
    float2 ta = __half22float2(*(__half2*)&ut.x), tb = __half22float2(*(__half2*)&ut.y);
    float4 bb = *(const float4*)&bias[lane * 4];
    float4 o;
    o.x = ax + sl * ta.x + bb.x;
    o.y = ay + sl * ta.y + bb.y;
    o.z = az + sl * tb.x + bb.z;
    o.w = aw + sl * tb.y + bb.w;
    *(float4*)&A[(size_t)node * 128 + lane * 4] = o;

    // fused per-graph sum / sumsq
    *(float4*)&s_red[0][wid][lane * 4] = o;
    float4 o2 = make_float4(o.x * o.x, o.y * o.y, o.z * o.z, o.w * o.w);
    *(float4*)&s_red[1][wid][lane * 4] = o2;
    __syncthreads();
    if (s_same) {
        if (tid < 128) {
            float t1 = 0.f, t2 = 0.f;
#pragma unroll
            for (int k = 0; k < 8; k++) { t1 += s_red[0][k][tid]; t2 += s_red[1][k][tid]; }
            atomicAdd(&gsum[s_g * 128 + tid], t1);
            atomicAdd(&gsq[s_g * 128 + tid], t2);
        }
    } else {
        int g = d_batch[node];
        atomicAdd(&gsum[g * 128 + lane * 4 + 0], o.x);
        atomicAdd(&gsum[g * 128 + lane * 4 + 1], o.y);
        atomicAdd(&gsum[g * 128 + lane * 4 + 2], o.z);
        atomicAdd(&gsum[g * 128 + lane * 4 + 3], o.w);
        atomicAdd(&gsq[g * 128 + lane * 4 + 0], o2.x);
        atomicAdd(&gsq[g * 128 + lane * 4 + 1], o2.y);
        atomicAdd(&gsq[g * 128 + lane * 4 + 2], o2.z);
        atomicAdd(&gsq[g * 128 + lane * 4 + 3], o2.w);
    }
}

// out = [in +] relu((A - alpha*mean)*rsqrt(var+eps)*gamma + beta)
// mean/var computed on the fly from raw per-graph sums.
template <int RES>
__global__ void final_kernel(const float* __restrict__ A, const float* __restrict__ in,
                             const float* __restrict__ alpha, const float* __restrict__ gamma,
                             const float* __restrict__ beta, float* __restrict__ out,
                             const float* __restrict__ gsum, const float* __restrict__ gsq) {
    int idx = blockIdx.x * blockDim.x + threadIdx.x;  // over N*32 float4s
    if (idx >= Nn * 32) return;
    int node = idx >> 5;
    int q = idx & 31;
    int g = d_batch[node];
    float inv = 1.f / d_gcntf[g];
    float4 a  = ((const float4*)A)[idx];
    float4 gs = *(const float4*)&gsum[g * 128 + q * 4];
    float4 gq = *(const float4*)&gsq[g * 128 + q * 4];
    float4 al = *(const float4*)&alpha[q * 4];
    float4 ga = *(const float4*)&gamma[q * 4];
    float4 be = *(const float4*)&beta[q * 4];
    float4 m, vv, o;
    m.x = gs.x * inv; m.y = gs.y * inv; m.z = gs.z * inv; m.w = gs.w * inv;
    vv.x = gq.x * inv - m.x * m.x * al.x * (2.f - al.x);
    vv.y = gq.y * inv - m.y * m.y * al.y * (2.f - al.y);
    vv.z = gq.z * inv - m.z * m.z * al.z * (2.f - al.z);
    vv.w = gq.w * inv - m.w * m.w * al.w * (2.f - al.w);
    o.x = fmaxf((a.x - al.x * m.x) * rsqrtf(vv.x + EPSc) * ga.x + be.x, 0.f);
    o.y = fmaxf((a.y - al.y * m.y) * rsqrtf(vv.y + EPSc) * ga.y + be.y, 0.f);
    o.z = fmaxf((a.z - al.z * m.z) * rsqrtf(vv.z + EPSc) * ga.z + be.z, 0.f);
    o.w = fmaxf((a.w - al.w * m.w) * rsqrtf(vv.w + EPSc) * ga.w + be.w, 0.f);
    if (RES) {
        float4 r = ((const float4*)in)[idx];
        o.x += r.x; o.y += r.y; o.z += r.z; o.w += r.w;
    }
    ((float4*)out)[idx] = o;
}

// ---------------- host orchestration ----------------
extern "C" void kernel_launch(void* const* d_in, const int* in_sizes, int n_in,
                              void* d_out, int out_size) {
    const float* x   = (const float*)d_in[0];
    const void*  ei  = d_in[1];
    const void*  bt  = d_in[2];
    const float* W1  = (const float*)d_in[3];
    const float* b1  = (const float*)d_in[4];
    const float* a1  = (const float*)d_in[5];
    const float* g1  = (const float*)d_in[6];
    const float* be1 = (const float*)d_in[7];
    const float* Wm  = (const float*)d_in[8];
    const float* bm  = (const float*)d_in[9];
    const float* am  = (const float*)d_in[10];
    const float* gm  = (const float*)d_in[11];
    const float* bem = (const float*)d_in[12];
    const float* WL  = (const float*)d_in[13];
    const float* bL  = (const float*)d_in[14];
    const float* aL  = (const float*)d_in[15];
    const float* gL  = (const float*)d_in[16];
    const float* beL = (const float*)d_in[17];
    const float* Wp1 = (const float*)d_in[18];
    const float* bp1 = (const float*)d_in[19];
    const float* Wp2 = (const float*)d_in[20];
    const float* bp2 = (const float*)d_in[21];
    float* out = (float*)d_out;

    float *HA, *HB, *A, *GS, *GQ;
    __half* Th;
    cudaGetSymbolAddress((void**)&HA, d_HA);
    cudaGetSymbolAddress((void**)&HB, d_HB);
    cudaGetSymbolAddress((void**)&Th, d_Th);
    cudaGetSymbolAddress((void**)&A,  d_A);
    cudaGetSymbolAddress((void**)&GS, d_gsum);
    cudaGetSymbolAddress((void**)&GQ, d_gsq);

    const int smem = (128 * XS_LD + 128 * WS_LD) * (int)sizeof(float);
    cudaFuncSetAttribute(gemm_tf32_half_kernel, cudaFuncAttributeMaxDynamicSharedMemorySize, smem);
    cudaFuncSetAttribute(gemm_tf32_head_kernel, cudaFuncAttributeMaxDynamicSharedMemorySize, smem);

    // ---- preprocessing (4 launches) ----
    zero_detect_kernel<<<NB_SCAN, 256>>>(ei);
    convert_hist_kernel<<<1024, 256>>>(ei, bt);
    scan_fused_kernel<<<NB_SCAN, 256>>>();
    scatter_kernel<<<(Ee + 255) / 256, 256>>>(ei);

    const int gemm_grid = (Nn + 127) / 128;
    const int agg_grid  = Nn / 8;   // 6250, exact
    const int elem_grid = (Nn * 32 + 511) / 512;
    const int GL = NGg * Hh;

    // ---- layer 1: x -> HB ----
    gemm_tf32_half_kernel<<<gemm_grid, 256, smem>>>(x, W1, Th, Nn);
    agg_kernel<<<agg_grid, 256>>>(Th, b1, A, GS + 0 * GL, GQ + 0 * GL);
    final_kernel<0><<<elem_grid, 512>>>(A, nullptr, a1, g1, be1, HB, GS + 0 * GL, GQ + 0 * GL);

    // ---- mid layer 0 (residual): HB -> HA ----
    gemm_tf32_half_kernel<<<gemm_grid, 256, smem>>>(HB, Wm + 0 * 128 * 128, Th, Nn);
    agg_kernel<<<agg_grid, 256>>>(Th, bm + 0 * 128, A, GS + 1 * GL, GQ + 1 * GL);
    final_kernel<1><<<elem_grid, 512>>>(A, HB, am + 0 * 128, gm + 0 * 128, bem + 0 * 128, HA,
                                        GS + 1 * GL, GQ + 1 * GL);

    // ---- mid layer 1 (residual): HA -> HB ----
    gemm_tf32_half_kernel<<<gemm_grid, 256, smem>>>(HA, Wm + 1 * 128 * 128, Th, Nn);
    agg_kernel<<<agg_grid, 256>>>(Th, bm + 1 * 128, A, GS + 2 * GL, GQ + 2 * GL);
    final_kernel<1><<<elem_grid, 512>>>(A, HA, am + 1 * 128, gm + 1 * 128, bem + 1 * 128, HB,
                                        GS + 2 * GL, GQ + 2 * GL);

    // ---- last layer: HB -> HA ----
    gemm_tf32_half_kernel<<<gemm_grid, 256, smem>>>(HB, WL, Th, Nn);
    agg_kernel<<<agg_grid, 256>>>(Th, bL, A, GS + 3 * GL, GQ + 3 * GL);
    final_kernel<0><<<elem_grid, 512>>>(A, nullptr, aL, gL, beL, HA, GS + 3 * GL, GQ + 3 * GL);

    // ---- predictor: HA -> out (tf32 GEMM with fused relu-MLP head) ----
    gemm_tf32_head_kernel<<<gemm_grid, 256, smem>>>(HA, Wp1, bp1, Wp2, bp2, out, Nn);
}

// round 7
// speedup vs baseline: 1.4195x; 1.0711x over previous
#include <cuda_runtime.h>
#include <cuda_fp16.h>
#include <math.h>

#define Nn 50000
#define Hh 128
#define Ee 800000
#define NGg 64
#define EPSc 1e-5f
#define NB_SCAN 196   // ceil(50000/256)

// ---------------- device scratch (static globals; no allocation) ----------------
// NOTE: all mutable state is zero at module load, and the LAST kernel of each
// launch (gemm_tf32_head_kernel epilogue) re-zeroes it, so every run (including
// the first) starts clean. This removes a dedicated zeroing launch.
__device__ int    d_batch[Nn];
__device__ int    d_deg[Nn];          // zeroed by head epilogue
__device__ float  d_dis[Nn];
__device__ int    d_rowptr[Nn + 1];
__device__ int    d_cursor[Nn];
__device__ int2   d_colw[Ee];
__device__ unsigned long long d_scan_state[NB_SCAN];  // zeroed by head epilogue
__device__ unsigned d_ticket;                          // zeroed by head epilogue
__device__ int    d_gstart[NGg + 1];
__device__ float  d_gcntf[NGg];
__device__ float  d_gsum[4 * NGg * Hh];  // zeroed by head epilogue
__device__ float  d_gsq[4 * NGg * Hh];   // zeroed by head epilogue
__device__ float  d_HA[(size_t)Nn * Hh];
__device__ float  d_HB[(size_t)Nn * Hh];
__device__ __half d_Th[(size_t)Nn * Hh];
__device__ float  d_A[(size_t)Nn * Hh];

// ---------------- dtype detection (per-block, no global state) ----------------
// int32 pairs read as int64 are >= 2^32 unless the high word is 0; 16 pairs all
// in [0, Nn) only happens for genuine int64 data.
__device__ __forceinline__ int detect_is64(const void* ei) {
    const long long* p = (const long long*)ei;
    int ok = 1;
#pragma unroll
    for (int k = 0; k < 16; k++) {
        long long v = p[k];
        if (v < 0 || v >= (long long)Nn) ok = 0;
    }
    return ok;
}

// ---------------- preprocessing ----------------

// convert batch to int32, histogram dst degrees (reads dst half of edge_index)
__global__ void convert_hist_kernel(const void* ei, const void* bt) {
    __shared__ int s_is64;
    if (threadIdx.x == 0) s_is64 = detect_is64(ei);
    __syncthreads();
    int is64 = s_is64;
    int stride = gridDim.x * blockDim.x;
    for (int i = blockIdx.x * blockDim.x + threadIdx.x; i < Ee; i += stride) {
        int v = is64 ? (int)((const long long*)ei)[Ee + i] : ((const int*)ei)[Ee + i];
        atomicAdd(&d_deg[v], 1);
    }
    for (int i = blockIdx.x * blockDim.x + threadIdx.x; i < Nn; i += stride) {
        int v = is64 ? (int)((const long long*)bt)[i] : ((const int*)bt)[i];
        d_batch[i] = v;
    }
}

// single-kernel decoupled-lookback scan of d_deg -> rowptr/cursor/dis,
// plus per-graph ranges (block 0).
__global__ void scan_fused_kernel() {
    __shared__ unsigned sbid;
    __shared__ int s_excl;
    __shared__ int sh[256];
    if (threadIdx.x == 0) sbid = atomicAdd(&d_ticket, 1u);
    __syncthreads();
    int b = (int)sbid;
    int idx = b * 256 + threadIdx.x;
    int deg = (idx < Nn) ? d_deg[idx] : 0;
    sh[threadIdx.x] = deg;
    __syncthreads();
    for (int off = 1; off < 256; off <<= 1) {
        int u = 0;
        if (threadIdx.x >= off) u = sh[threadIdx.x - off];
        __syncthreads();
        if (threadIdx.x >= off) sh[threadIdx.x] += u;
        __syncthreads();
    }
    int incl = sh[threadIdx.x];
    int aggr = sh[255];
    if (threadIdx.x == 0) {
        if (b == 0) {
            atomicExch(&d_scan_state[0], (2ull << 32) | (unsigned)aggr);
            s_excl = 0;
        } else {
            atomicExch(&d_scan_state[b], (1ull << 32) | (unsigned)aggr);
            int excl = 0;
            int j = b - 1;
            while (true) {
                unsigned long long st;
                do { st = atomicAdd(&d_scan_state[j], 0ull); } while ((st >> 32) == 0ull);
                excl += (int)(unsigned)st;
                if ((st >> 32) == 2ull) break;
                j--;
            }
            atomicExch(&d_scan_state[b], (2ull << 32) | (unsigned)(excl + aggr));
            s_excl = excl;
        }
    }
    __syncthreads();
    int excl = s_excl;
    if (idx < Nn) {
        d_rowptr[idx + 1] = excl + incl;
        if (idx == 0) d_rowptr[0] = 0;
        d_cursor[idx] = excl + incl - deg;
        d_dis[idx] = rsqrtf((float)deg + 1.0f);
    }
    if (b == 0) {
        int t = threadIdx.x;
        if (t <= NGg) {
            int lo = 0, hi = Nn;
            while (lo < hi) {
                int mid = (lo + hi) >> 1;
                if (d_batch[mid] < t) lo = mid + 1; else hi = mid;
            }
            d_gstart[t] = lo;
        }
        __syncthreads();
        if (t < NGg) {
            int c = d_gstart[t + 1] - d_gstart[t];
            d_gcntf[t] = (c > 0) ? (float)c : 1.0f;
        }
    }
}

// scatter edges into CSR; reads edge_index directly
__global__ void scatter_kernel(const void* ei) {
    __shared__ int s_is64;
    if (threadIdx.x == 0) s_is64 = detect_is64(ei);
    __syncthreads();
    int i = blockIdx.x * blockDim.x + threadIdx.x;
    if (i >= Ee) return;
    int s, dd;
    if (s_is64) {
        s  = (int)((const long long*)ei)[i];
        dd = (int)((const long long*)ei)[Ee + i];
    } else {
        s  = ((const int*)ei)[i];
        dd = ((const int*)ei)[Ee + i];
    }
    int pos = atomicAdd(&d_cursor[dd], 1);
    d_colw[pos] = make_int2(s, __float_as_int(d_dis[s] * d_dis[dd]));
}

// ---------------- tf32 tensor-core GEMM (64-row tiles, occupancy 2) -----------
// Y[n,128] = X[n,128] @ W[128,128]. 256 threads = 8 warps:
//   wy = warp & 3  -> rows wy*16 .. wy*16+15
//   wx = warp >> 2 -> cols wx*64 .. wx*64+63  (8 n8-tiles)
// Xs [64][132] row-major (A-frag bank = 4*qr + qc, conflict-free)
// Ws [128][136] [k][n]   (B-frag bank = 8*qc + qr + const, conflict-free)
#define XS_LD 132
#define WS_LD 136
#define TILE_M 64

__device__ __forceinline__ unsigned f2tf32(float v) {
    unsigned o;
    asm("cvt.rna.tf32.f32 %0, %1;" : "=r"(o) : "f"(v));
    return o;
}

#define TF32_GEMM_CORE()                                                          \
    extern __shared__ float sh[];                                                 \
    float* Xs = sh;                                                               \
    float* Ws = sh + TILE_M * XS_LD;                                              \
    const int tid = threadIdx.x;                                                  \
    const int row0 = blockIdx.x * TILE_M;                                         \
    _Pragma("unroll")                                                             \
    for (int i = 0; i < 16; i++) {                                                \
        int idx = i * 256 + tid;                                                  \
        int r = idx >> 5;                                                         \
        int c = (idx & 31) * 4;                                                   \
        float4 wv = *(const float4*)&W[r * 128 + c];                              \
        Ws[r * WS_LD + c + 0] = __uint_as_float(f2tf32(wv.x));                    \
        Ws[r * WS_LD + c + 1] = __uint_as_float(f2tf32(wv.y));                    \
        Ws[r * WS_LD + c + 2] = __uint_as_float(f2tf32(wv.z));                    \
        Ws[r * WS_LD + c + 3] = __uint_as_float(f2tf32(wv.w));                    \
    }                                                                             \
    _Pragma("unroll")                                                             \
    for (int i = 0; i < 8; i++) {                                                 \
        int idx = i * 256 + tid;                                                  \
        int r = idx >> 5;                                                         \
        int c = (idx & 31) * 4;                                                   \
        float4 xv = make_float4(0.f, 0.f, 0.f, 0.f);                              \
        if (row0 + r < n) xv = *(const float4*)&X[(size_t)(row0 + r) * 128 + c];  \
        Xs[r * XS_LD + c + 0] = __uint_as_float(f2tf32(xv.x));                    \
        Xs[r * XS_LD + c + 1] = __uint_as_float(f2tf32(xv.y));                    \
        Xs[r * XS_LD + c + 2] = __uint_as_float(f2tf32(xv.z));                    \
        Xs[r * XS_LD + c + 3] = __uint_as_float(f2tf32(xv.w));                    \
    }                                                                             \
    __syncthreads();                                                              \
    const int warp = tid >> 5;                                                    \
    const int lane = tid & 31;                                                    \
    const int qr = lane >> 2;                                                     \
    const int qc = lane & 3;                                                      \
    const int wy = warp & 3;                                                      \
    const int wx = warp >> 2;                                                     \
    const int m0 = wy * 16;                                                       \
    const int n0 = wx * 64;                                                       \
    float acc[8][4];                                                              \
    _Pragma("unroll")                                                             \
    for (int t = 0; t < 8; t++) {                                                 \
        acc[t][0] = 0.f; acc[t][1] = 0.f; acc[t][2] = 0.f; acc[t][3] = 0.f;       \
    }                                                                             \
    _Pragma("unroll 4")                                                           \
    for (int k0 = 0; k0 < 128; k0 += 8) {                                         \
        unsigned a0 = __float_as_uint(Xs[(m0 + qr)     * XS_LD + k0 + qc]);       \
        unsigned a1 = __float_as_uint(Xs[(m0 + qr + 8) * XS_LD + k0 + qc]);       \
        unsigned a2 = __float_as_uint(Xs[(m0 + qr)     * XS_LD + k0 + qc + 4]);   \
        unsigned a3 = __float_as_uint(Xs[(m0 + qr + 8) * XS_LD + k0 + qc + 4]);   \
        _Pragma("unroll")                                                         \
        for (int t = 0; t < 8; t++) {                                             \
            int cc = n0 + t * 8 + qr;                                             \
            unsigned b0 = __float_as_uint(Ws[(k0 + qc)     * WS_LD + cc]);        \
            unsigned b1 = __float_as_uint(Ws[(k0 + qc + 4) * WS_LD + cc]);        \
            asm volatile(                                                         \
                "mma.sync.aligned.m16n8k8.row.col.f32.tf32.tf32.f32 "             \
                "{%0,%1,%2,%3}, {%4,%5,%6,%7}, {%8,%9}, {%0,%1,%2,%3};"           \
                : "+f"(acc[t][0]), "+f"(acc[t][1]),                               \
                  "+f"(acc[t][2]), "+f"(acc[t][3])                                \
                : "r"(a0), "r"(a1), "r"(a2), "r"(a3), "r"(b0), "r"(b1));          \
        }                                                                         \
    }                                                                             \
    const int r_lo = row0 + m0 + qr;                                              \
    const int r_hi = r_lo + 8;

// fp16-output GEMM (feeds edge gather)
__global__ __launch_bounds__(256) void gemm_tf32_half_kernel(
    const float* __restrict__ X, const float* __restrict__ W,
    __half* __restrict__ Y, int n) {
    TF32_GEMM_CORE()
    if (r_lo < n) {
#pragma unroll
        for (int t = 0; t < 8; t++)
            *(__half2*)&Y[(size_t)r_lo * 128 + n0 + t * 8 + qc * 2] =
                __floats2half2_rn(acc[t][0], acc[t][1]);
    }
    if (r_hi < n) {
#pragma unroll
        for (int t = 0; t < 8; t++)
            *(__half2*)&Y[(size_t)r_hi * 128 + n0 + t * 8 + qc * 2] =
                __floats2half2_rn(acc[t][2], acc[t][3]);
    }
}

// final GEMM with fused predictor head + end-of-run state cleanup.
// out[r] = sigmoid( sum_c relu(acc[r][c]+bp1[c]) * Wp2[c] + bp2 )
__global__ __launch_bounds__(256) void gemm_tf32_head_kernel(
    const float* __restrict__ X, const float* __restrict__ W,
    const float* __restrict__ bp1, const float* __restrict__ Wp2,
    const float* __restrict__ bp2, float* __restrict__ out, int n) {
    TF32_GEMM_CORE()
    float p_lo = 0.f, p_hi = 0.f;
#pragma unroll
    for (int t = 0; t < 8; t++) {
        int c = n0 + t * 8 + qc * 2;
        float b0v = bp1[c], b1v = bp1[c + 1];
        float w0v = Wp2[c], w1v = Wp2[c + 1];
        p_lo += fmaxf(acc[t][0] + b0v, 0.f) * w0v + fmaxf(acc[t][1] + b1v, 0.f) * w1v;
        p_hi += fmaxf(acc[t][2] + b0v, 0.f) * w0v + fmaxf(acc[t][3] + b1v, 0.f) * w1v;
    }
    // reduce over the 4 lanes of each row quad
    p_lo += __shfl_xor_sync(0xffffffffu, p_lo, 1);
    p_lo += __shfl_xor_sync(0xffffffffu, p_lo, 2);
    p_hi += __shfl_xor_sync(0xffffffffu, p_hi, 1);
    p_hi += __shfl_xor_sync(0xffffffffu, p_hi, 2);
    // cross-warp reduce (wx=0 and wx=1 halves) via smem (reuse dynamic smem)
    __syncthreads();
    float* s_head = sh;  // 64 rows x 2 halves
    if (qc == 0) {
        s_head[(m0 + qr) * 2 + wx]     = p_lo;
        s_head[(m0 + qr + 8) * 2 + wx] = p_hi;
    }
    __syncthreads();
    if (tid < TILE_M) {
        int gr = row0 + tid;
        if (gr < n) {
            float z = s_head[tid * 2] + s_head[tid * 2 + 1] + bp2[0];
            out[gr] = 1.f / (1.f + expf(-z));
        }
    }
    // ---- state cleanup for the next run (this is the last kernel) ----
    int gt = blockIdx.x * 256 + tid;
    if (gt < Nn) d_deg[gt] = 0;
    if (gt < NB_SCAN) d_scan_state[gt] = 0ull;
    if (gt == 0) d_ticket = 0u;
    if (gt < 4 * NGg * Hh) { d_gsum[gt] = 0.f; d_gsq[gt] = 0.f; }
}

// ---------------- CSR aggregation + fused per-graph sum/sumsq -----------------
// grid = 6250 blocks x 256 threads; warp w of block b handles node b*8+w (exact).
__global__ void agg_kernel(const __half* __restrict__ T, const float* __restrict__ bias,
                           float* __restrict__ A,
                           float* __restrict__ gsum, float* __restrict__ gsq) {
    __shared__ __align__(16) float s_red[2][8][132];
    __shared__ int s_same, s_g;
    int tid = threadIdx.x;
    int wid = tid >> 5;
    int lane = tid & 31;
    int node = blockIdx.x * 8 + wid;
    if (tid == 0) {
        int g0 = d_batch[blockIdx.x * 8];
        int g7 = d_batch[blockIdx.x * 8 + 7];
        s_same = (g0 == g7);
        s_g = g0;
    }
    int s = d_rowptr[node], e = d_rowptr[node + 1];
    float ax = 0.f, ay = 0.f, az = 0.f, aw = 0.f;
    int p = s;
    for (; p + 4 <= e; p += 4) {
        int2 e0 = d_colw[p], e1 = d_colw[p + 1], e2 = d_colw[p + 2], e3 = d_colw[p + 3];
        float w0 = __int_as_float(e0.y), w1 = __int_as_float(e1.y);
        float w2 = __int_as_float(e2.y), w3 = __int_as_float(e3.y);
        uint2 u0 = ((const uint2*)(T + (size_t)e0.x * 128))[lane];
        uint2 u1 = ((const uint2*)(T + (size_t)e1.x * 128))[lane];
        uint2 u2 = ((const uint2*)(T + (size_t)e2.x * 128))[lane];
        uint2 u3 = ((const uint2*)(T + (size_t)e3.x * 128))[lane];
        float2 a0 = __half22float2(*(__half2*)&u0.x), b0 = __half22float2(*(__half2*)&u0.y);
        float2 a1 = __half22float2(*(__half2*)&u1.x), b1 = __half22float2(*(__half2*)&u1.y);
        float2 a2 = __half22float2(*(__half2*)&u2.x), b2 = __half22float2(*(__half2*)&u2.y);
        float2 a3 = __half22float2(*(__half2*)&u3.x), b3 = __half22float2(*(__half2*)&u3.y);
        ax += w0 * a0.x + w1 * a1.x + w2 * a2.x + w3 * a3.x;
        ay += w0 * a0.y + w1 * a1.y + w2 * a2.y + w3 * a3.y;
        az += w0 * b0.x + w1 * b1.x + w2 * b2.x + w3 * b3.x;
        aw += w0 * b0.y + w1 * b1.y + w2 * b2.y + w3 * b3.y;
    }
    for (; p < e; p++) {
        int2 ec = d_colw[p];
        float w = __int_as_float(ec.y);
        uint2 u = ((const uint2*)(T + (size_t)ec.x * 128))[lane];
        float2 a = __half22float2(*(__half2*)&u.x), b = __half22float2(*(__half2*)&u.y);
        ax += w * a.x; ay += w * a.y; az += w * b.x; aw += w * b.y;
    }
    float ds = d_dis[node];
    float sl = ds * ds;
    uint2 ut = ((const uint2*)(T + (size_t)node * 128))[lane];
    float2 ta = __half22float2(*(__half2*)&ut.x), tb = __half22float2(*(__half2*)&ut.y);
    float4 bb = *(const float4*)&bias[lane * 4];
    float4 o;
    o.x = ax + sl * ta.x + bb.x;
    o.y = ay + sl * ta.y + bb.y;
    o.z = az + sl * tb.x + bb.z;
    o.w = aw + sl * tb.y + bb.w;
    *(float4*)&A[(size_t)node * 128 + lane * 4] = o;

    // fused per-graph sum / sumsq
    *(float4*)&s_red[0][wid][lane * 4] = o;
    float4 o2 = make_float4(o.x * o.x, o.y * o.y, o.z * o.z, o.w * o.w);
    *(float4*)&s_red[1][wid][lane * 4] = o2;
    __syncthreads();
    if (s_same) {
        if (tid < 128) {
            float t1 = 0.f, t2 = 0.f;
#pragma unroll
            for (int k = 0; k < 8; k++) { t1 += s_red[0][k][tid]; t2 += s_red[1][k][tid]; }
            atomicAdd(&gsum[s_g * 128 + tid], t1);
            atomicAdd(&gsq[s_g * 128 + tid], t2);
        }
    } else {
        int g = d_batch[node];
        atomicAdd(&gsum[g * 128 + lane * 4 + 0], o.x);
        atomicAdd(&gsum[g * 128 + lane * 4 + 1], o.y);
        atomicAdd(&gsum[g * 128 + lane * 4 + 2], o.z);
        atomicAdd(&gsum[g * 128 + lane * 4 + 3], o.w);
        atomicAdd(&gsq[g * 128 + lane * 4 + 0], o2.x);
        atomicAdd(&gsq[g * 128 + lane * 4 + 1], o2.y);
        atomicAdd(&gsq[g * 128 + lane * 4 + 2], o2.z);
        atomicAdd(&gsq[g * 128 + lane * 4 + 3], o2.w);
    }
}

// out = [in +] relu((A - alpha*mean)*rsqrt(var+eps)*gamma + beta)
// mean/var computed on the fly from raw per-graph sums.
template <int RES>
__global__ void final_kernel(const float* __restrict__ A, const float* __restrict__ in,
                             const float* __restrict__ alpha, const float* __restrict__ gamma,
                             const float* __restrict__ beta, float* __restrict__ out,
                             const float* __restrict__ gsum, const float* __restrict__ gsq) {
    int idx = blockIdx.x * blockDim.x + threadIdx.x;  // over N*32 float4s
    if (idx >= Nn * 32) return;
    int node = idx >> 5;
    int q = idx & 31;
    int g = d_batch[node];
    float inv = 1.f / d_gcntf[g];
    float4 a  = ((const float4*)A)[idx];
    float4 gs = *(const float4*)&gsum[g * 128 + q * 4];
    float4 gq = *(const float4*)&gsq[g * 128 + q * 4];
    float4 al = *(const float4*)&alpha[q * 4];
    float4 ga = *(const float4*)&gamma[q * 4];
    float4 be = *(const float4*)&beta[q * 4];
    float4 m, vv, o;
    m.x = gs.x * inv; m.y = gs.y * inv; m.z = gs.z * inv; m.w = gs.w * inv;
    vv.x = gq.x * inv - m.x * m.x * al.x * (2.f - al.x);
    vv.y = gq.y * inv - m.y * m.y * al.y * (2.f - al.y);
    vv.z = gq.z * inv - m.z * m.z * al.z * (2.f - al.z);
    vv.w = gq.w * inv - m.w * m.w * al.w * (2.f - al.w);
    o.x = fmaxf((a.x - al.x * m.x) * rsqrtf(vv.x + EPSc) * ga.x + be.x, 0.f);
    o.y = fmaxf((a.y - al.y * m.y) * rsqrtf(vv.y + EPSc) * ga.y + be.y, 0.f);
    o.z = fmaxf((a.z - al.z * m.z) * rsqrtf(vv.z + EPSc) * ga.z + be.z, 0.f);
    o.w = fmaxf((a.w - al.w * m.w) * rsqrtf(vv.w + EPSc) * ga.w + be.w, 0.f);
    if (RES) {
        float4 r = ((const float4*)in)[idx];
        o.x += r.x; o.y += r.y; o.z += r.z; o.w += r.w;
    }
    ((float4*)out)[idx] = o;
}

// ---------------- host orchestration ----------------
extern "C" void kernel_launch(void* const* d_in, const int* in_sizes, int n_in,
                              void* d_out, int out_size) {
    const float* x   = (const float*)d_in[0];
    const void*  ei  = d_in[1];
    const void*  bt  = d_in[2];
    const float* W1  = (const float*)d_in[3];
    const float* b1  = (const float*)d_in[4];
    const float* a1  = (const float*)d_in[5];
    const float* g1  = (const float*)d_in[6];
    const float* be1 = (const float*)d_in[7];
    const float* Wm  = (const float*)d_in[8];
    const float* bm  = (const float*)d_in[9];
    const float* am  = (const float*)d_in[10];
    const float* gm  = (const float*)d_in[11];
    const float* bem = (const float*)d_in[12];
    const float* WL  = (const float*)d_in[13];
    const float* bL  = (const float*)d_in[14];
    const float* aL  = (const float*)d_in[15];
    const float* gL  = (const float*)d_in[16];
    const float* beL = (const float*)d_in[17];
    const float* Wp1 = (const float*)d_in[18];
    const float* bp1 = (const float*)d_in[19];
    const float* Wp2 = (const float*)d_in[20];
    const float* bp2 = (const float*)d_in[21];
    float* out = (float*)d_out;

    float *HA, *HB, *A, *GS, *GQ;
    __half* Th;
    cudaGetSymbolAddress((void**)&HA, d_HA);
    cudaGetSymbolAddress((void**)&HB, d_HB);
    cudaGetSymbolAddress((void**)&Th, d_Th);
    cudaGetSymbolAddress((void**)&A,  d_A);
    cudaGetSymbolAddress((void**)&GS, d_gsum);
    cudaGetSymbolAddress((void**)&GQ, d_gsq);

    const int smem = (TILE_M * XS_LD + 128 * WS_LD) * (int)sizeof(float);
    cudaFuncSetAttribute(gemm_tf32_half_kernel, cudaFuncAttributeMaxDynamicSharedMemorySize, smem);
    cudaFuncSetAttribute(gemm_tf32_head_kernel, cudaFuncAttributeMaxDynamicSharedMemorySize, smem);

    // ---- preprocessing (3 launches; state zeroing done by previous run's tail) ----
    convert_hist_kernel<<<1024, 256>>>(ei, bt);
    scan_fused_kernel<<<NB_SCAN, 256>>>();
    scatter_kernel<<<(Ee + 255) / 256, 256>>>(ei);

    const int gemm_grid = (Nn + TILE_M - 1) / TILE_M;  // 782
    const int agg_grid  = Nn / 8;   // 6250, exact
    const int elem_grid = (Nn * 32 + 511) / 512;
    const int GL = NGg * Hh;

    // ---- layer 1: x -> HB ----
    gemm_tf32_half_kernel<<<gemm_grid, 256, smem>>>(x, W1, Th, Nn);
    agg_kernel<<<agg_grid, 256>>>(Th, b1, A, GS + 0 * GL, GQ + 0 * GL);
    final_kernel<0><<<elem_grid, 512>>>(A, nullptr, a1, g1, be1, HB, GS + 0 * GL, GQ + 0 * GL);

    // ---- mid layer 0 (residual): HB -> HA ----
    gemm_tf32_half_kernel<<<gemm_grid, 256, smem>>>(HB, Wm + 0 * 128 * 128, Th, Nn);
    agg_kernel<<<agg_grid, 256>>>(Th, bm + 0 * 128, A, GS + 1 * GL, GQ + 1 * GL);
    final_kernel<1><<<elem_grid, 512>>>(A, HB, am + 0 * 128, gm + 0 * 128, bem + 0 * 128, HA,
                                        GS + 1 * GL, GQ + 1 * GL);

    // ---- mid layer 1 (residual): HA -> HB ----
    gemm_tf32_half_kernel<<<gemm_grid, 256, smem>>>(HA, Wm + 1 * 128 * 128, Th, Nn);
    agg_kernel<<<agg_grid, 256>>>(Th, bm + 1 * 128, A, GS + 2 * GL, GQ + 2 * GL);
    final_kernel<1><<<elem_grid, 512>>>(A, HA, am + 1 * 128, gm + 1 * 128, bem + 1 * 128, HB,
                                        GS + 2 * GL, GQ + 2 * GL);

    // ---- last layer: HB -> HA ----
    gemm_tf32_half_kernel<<<gemm_grid, 256, smem>>>(HB, WL, Th, Nn);
    agg_kernel<<<agg_grid, 256>>>(Th, bL, A, GS + 3 * GL, GQ + 3 * GL);
    final_kernel<0><<<elem_grid, 512>>>(A, nullptr, aL, gL, beL, HA, GS + 3 * GL, GQ + 3 * GL);

    // ---- predictor: HA -> out (GEMM + fused head + state cleanup) ----
    gemm_tf32_head_kernel<<<gemm_grid, 256, smem>>>(HA, Wp1, bp1, Wp2, bp2, out, Nn);
}

// round 8
// speedup vs baseline: 1.6297x; 1.1481x over previous
#include <cuda_runtime.h>
#include <cuda_fp16.h>
#include <math.h>

#define Nn 50000
#define Hh 128
#define Ee 800000
#define NGg 64
#define EPSc 1e-5f
#define NB_SCAN 196   // ceil(50000/256)

// ---------------- device scratch (static globals; no allocation) ----------------
// All mutable state is zero at module load; the LAST kernel of each run
// (gemm_fp16_head_kernel epilogue) re-zeroes it, so every run starts clean.
__device__ int    d_batch[Nn];
__device__ int    d_deg[Nn];          // zeroed by head epilogue
__device__ float  d_dis[Nn];
__device__ int    d_rowptr[Nn + 1];
__device__ int    d_cursor[Nn];
__device__ int2   d_colw[Ee];
__device__ unsigned long long d_scan_state[NB_SCAN];  // zeroed by head epilogue
__device__ unsigned d_ticket;                          // zeroed by head epilogue
__device__ int    d_gstart[NGg + 1];
__device__ float  d_gcntf[NGg];
__device__ float  d_gsum[4 * NGg * Hh];  // zeroed by head epilogue
__device__ float  d_gsq[4 * NGg * Hh];   // zeroed by head epilogue
__device__ float  d_HA[(size_t)Nn * Hh];
__device__ float  d_HB[(size_t)Nn * Hh];
__device__ __half d_Th[(size_t)Nn * Hh];
__device__ float  d_A[(size_t)Nn * Hh];

// ---------------- dtype detection (per-block, no global state) ----------------
__device__ __forceinline__ int detect_is64(const void* ei) {
    const long long* p = (const long long*)ei;
    int ok = 1;
#pragma unroll
    for (int k = 0; k < 16; k++) {
        long long v = p[k];
        if (v < 0 || v >= (long long)Nn) ok = 0;
    }
    return ok;
}

// ---------------- preprocessing ----------------

__global__ void convert_hist_kernel(const void* ei, const void* bt) {
    __shared__ int s_is64;
    if (threadIdx.x == 0) s_is64 = detect_is64(ei);
    __syncthreads();
    int is64 = s_is64;
    int stride = gridDim.x * blockDim.x;
    for (int i = blockIdx.x * blockDim.x + threadIdx.x; i < Ee; i += stride) {
        int v = is64 ? (int)((const long long*)ei)[Ee + i] : ((const int*)ei)[Ee + i];
        atomicAdd(&d_deg[v], 1);
    }
    for (int i = blockIdx.x * blockDim.x + threadIdx.x; i < Nn; i += stride) {
        int v = is64 ? (int)((const long long*)bt)[i] : ((const int*)bt)[i];
        d_batch[i] = v;
    }
}

// decoupled-lookback scan of d_deg -> rowptr/cursor/dis + per-graph ranges
__global__ void scan_fused_kernel() {
    __shared__ unsigned sbid;
    __shared__ int s_excl;
    __shared__ int sh[256];
    if (threadIdx.x == 0) sbid = atomicAdd(&d_ticket, 1u);
    __syncthreads();
    int b = (int)sbid;
    int idx = b * 256 + threadIdx.x;
    int deg = (idx < Nn) ? d_deg[idx] : 0;
    sh[threadIdx.x] = deg;
    __syncthreads();
    for (int off = 1; off < 256; off <<= 1) {
        int u = 0;
        if (threadIdx.x >= off) u = sh[threadIdx.x - off];
        __syncthreads();
        if (threadIdx.x >= off) sh[threadIdx.x] += u;
        __syncthreads();
    }
    int incl = sh[threadIdx.x];
    int aggr = sh[255];
    if (threadIdx.x == 0) {
        if (b == 0) {
            atomicExch(&d_scan_state[0], (2ull << 32) | (unsigned)aggr);
            s_excl = 0;
        } else {
            atomicExch(&d_scan_state[b], (1ull << 32) | (unsigned)aggr);
            int excl = 0;
            int j = b - 1;
            while (true) {
                unsigned long long st;
                do { st = atomicAdd(&d_scan_state[j], 0ull); } while ((st >> 32) == 0ull);
                excl += (int)(unsigned)st;
                if ((st >> 32) == 2ull) break;
                j--;
            }
            atomicExch(&d_scan_state[b], (2ull << 32) | (unsigned)(excl + aggr));
            s_excl = excl;
        }
    }
    __syncthreads();
    int excl = s_excl;
    if (idx < Nn) {
        d_rowptr[idx + 1] = excl + incl;
        if (idx == 0) d_rowptr[0] = 0;
        d_cursor[idx] = excl + incl - deg;
        d_dis[idx] = rsqrtf((float)deg + 1.0f);
    }
    if (b == 0) {
        int t = threadIdx.x;
        if (t <= NGg) {
            int lo = 0, hi = Nn;
            while (lo < hi) {
                int mid = (lo + hi) >> 1;
                if (d_batch[mid] < t) lo = mid + 1; else hi = mid;
            }
            d_gstart[t] = lo;
        }
        __syncthreads();
        if (t < NGg) {
            int c = d_gstart[t + 1] - d_gstart[t];
            d_gcntf[t] = (c > 0) ? (float)c : 1.0f;
        }
    }
}

__global__ void scatter_kernel(const void* ei) {
    __shared__ int s_is64;
    if (threadIdx.x == 0) s_is64 = detect_is64(ei);
    __syncthreads();
    int i = blockIdx.x * blockDim.x + threadIdx.x;
    if (i >= Ee) return;
    int s, dd;
    if (s_is64) {
        s  = (int)((const long long*)ei)[i];
        dd = (int)((const long long*)ei)[Ee + i];
    } else {
        s  = ((const int*)ei)[i];
        dd = ((const int*)ei)[Ee + i];
    }
    int pos = atomicAdd(&d_cursor[dd], 1);
    d_colw[pos] = make_int2(s, __float_as_int(d_dis[s] * d_dis[dd]));
}

// ---------------- fp16 tensor-core GEMM (ldmatrix + mma.m16n8k16) -------------
// Y[n,128] = X[n,128] @ W[128,128]; fp32 in, fp16 operands (10-bit mantissa,
// same as tf32), fp32 accumulate. 256 threads = 8 warps:
//   wy = warp & 3  -> rows wy*16..+15 ;  wx = warp >> 2 -> cols wx*64..+63
// Xs [64][136] halves (row pitch 272 B), Ws [128][136] halves, [k][n] natural.
// A-frags: ldmatrix.x4 ; B-frags: ldmatrix.x4.trans (W stays k-major).
#define XPITCH 136
#define WPITCH 136
#define TILE_M 64
#define GEMM_SMEM ((TILE_M * XPITCH + 128 * WPITCH) * 2)

__device__ __forceinline__ void ldm_x4(unsigned& r0, unsigned& r1, unsigned& r2,
                                       unsigned& r3, unsigned addr) {
    asm volatile("ldmatrix.sync.aligned.m8n8.x4.shared.b16 {%0,%1,%2,%3}, [%4];"
                 : "=r"(r0), "=r"(r1), "=r"(r2), "=r"(r3) : "r"(addr));
}
__device__ __forceinline__ void ldm_x4t(unsigned& r0, unsigned& r1, unsigned& r2,
                                        unsigned& r3, unsigned addr) {
    asm volatile("ldmatrix.sync.aligned.m8n8.x4.trans.shared.b16 {%0,%1,%2,%3}, [%4];"
                 : "=r"(r0), "=r"(r1), "=r"(r2), "=r"(r3) : "r"(addr));
}

__device__ __forceinline__ uint2 f4_to_h4(float4 v) {
    uint2 o;
    *(__half2*)&o.x = __floats2half2_rn(v.x, v.y);
    *(__half2*)&o.y = __floats2half2_rn(v.z, v.w);
    return o;
}

#define FP16_GEMM_CORE()                                                          \
    extern __shared__ __align__(16) char smem_raw[];                              \
    __half* Xs = (__half*)smem_raw;                                               \
    __half* Ws = Xs + TILE_M * XPITCH;                                            \
    const int tid = threadIdx.x;                                                  \
    const int row0 = blockIdx.x * TILE_M;                                         \
    _Pragma("unroll")                                                             \
    for (int i = 0; i < 16; i++) {                                                \
        int idx = i * 256 + tid;                                                  \
        int r = idx >> 5;                                                         \
        int c = (idx & 31) * 4;                                                   \
        *(uint2*)&Ws[r * WPITCH + c] = f4_to_h4(*(const float4*)&W[r * 128 + c]); \
    }                                                                             \
    _Pragma("unroll")                                                             \
    for (int i = 0; i < 8; i++) {                                                 \
        int idx = i * 256 + tid;                                                  \
        int r = idx >> 5;                                                         \
        int c = (idx & 31) * 4;                                                   \
        float4 xv = make_float4(0.f, 0.f, 0.f, 0.f);                              \
        if (row0 + r < n) xv = *(const float4*)&X[(size_t)(row0 + r) * 128 + c];  \
        *(uint2*)&Xs[r * XPITCH + c] = f4_to_h4(xv);                              \
    }                                                                             \
    __syncthreads();                                                              \
    const int warp = tid >> 5;                                                    \
    const int lane = tid & 31;                                                    \
    const int qr = lane >> 2;                                                     \
    const int qc = lane & 3;                                                      \
    const int wy = warp & 3;                                                      \
    const int wx = warp >> 2;                                                     \
    const int m0 = wy * 16;                                                       \
    const int n0 = wx * 64;                                                       \
    const int trow = lane & 7;                                                    \
    const int tsel = lane >> 3;                                                   \
    unsigned xs_b = (unsigned)__cvta_generic_to_shared(Xs);                       \
    unsigned ws_b = (unsigned)__cvta_generic_to_shared(Ws);                       \
    unsigned a_addr = xs_b +                                                      \
        ((m0 + trow + 8 * (tsel & 1)) * XPITCH + 8 * (tsel >> 1)) * 2;            \
    unsigned b_addr = ws_b +                                                      \
        ((trow + 8 * (tsel & 1)) * WPITCH + n0 + 8 * (tsel >> 1)) * 2;            \
    float acc[8][4];                                                              \
    _Pragma("unroll")                                                             \
    for (int t = 0; t < 8; t++) {                                                 \
        acc[t][0] = 0.f; acc[t][1] = 0.f; acc[t][2] = 0.f; acc[t][3] = 0.f;       \
    }                                                                             \
    _Pragma("unroll")                                                             \
    for (int ks = 0; ks < 8; ks++) {                                              \
        unsigned a0, a1, a2, a3;                                                  \
        ldm_x4(a0, a1, a2, a3, a_addr + ks * 32);                                 \
        _Pragma("unroll")                                                         \
        for (int tp = 0; tp < 4; tp++) {                                          \
            unsigned b0, b1, b2, b3;                                              \
            ldm_x4t(b0, b1, b2, b3, b_addr + ks * (16 * WPITCH * 2) + tp * 32);   \
            asm volatile(                                                         \
                "mma.sync.aligned.m16n8k16.row.col.f32.f16.f16.f32 "              \
                "{%0,%1,%2,%3}, {%4,%5,%6,%7}, {%8,%9}, {%0,%1,%2,%3};"           \
                : "+f"(acc[2 * tp][0]), "+f"(acc[2 * tp][1]),                     \
                  "+f"(acc[2 * tp][2]), "+f"(acc[2 * tp][3])                      \
                : "r"(a0), "r"(a1), "r"(a2), "r"(a3), "r"(b0), "r"(b1));          \
            asm volatile(                                                         \
                "mma.sync.aligned.m16n8k16.row.col.f32.f16.f16.f32 "              \
                "{%0,%1,%2,%3}, {%4,%5,%6,%7}, {%8,%9}, {%0,%1,%2,%3};"           \
                : "+f"(acc[2 * tp + 1][0]), "+f"(acc[2 * tp + 1][1]),             \
                  "+f"(acc[2 * tp + 1][2]), "+f"(acc[2 * tp + 1][3])              \
                : "r"(a0), "r"(a1), "r"(a2), "r"(a3), "r"(b2), "r"(b3));          \
        }                                                                         \
    }                                                                             \
    const int r_lo = row0 + m0 + qr;                                              \
    const int r_hi = r_lo + 8;

// fp16-output GEMM (feeds edge gather)
__global__ __launch_bounds__(256) void gemm_fp16_half_kernel(
    const float* __restrict__ X, const float* __restrict__ W,
    __half* __restrict__ Y, int n) {
    FP16_GEMM_CORE()
    if (r_lo < n) {
#pragma unroll
        for (int t = 0; t < 8; t++)
            *(__half2*)&Y[(size_t)r_lo * 128 + n0 + t * 8 + qc * 2] =
                __floats2half2_rn(acc[t][0], acc[t][1]);
    }
    if (r_hi < n) {
#pragma unroll
        for (int t = 0; t < 8; t++)
            *(__half2*)&Y[(size_t)r_hi * 128 + n0 + t * 8 + qc * 2] =
                __floats2half2_rn(acc[t][2], acc[t][3]);
    }
}

// final GEMM with fused predictor head + end-of-run state cleanup.
__global__ __launch_bounds__(256) void gemm_fp16_head_kernel(
    const float* __restrict__ X, const float* __restrict__ W,
    const float* __restrict__ bp1, const float* __restrict__ Wp2,
    const float* __restrict__ bp2, float* __restrict__ out, int n) {
    FP16_GEMM_CORE()
    float p_lo = 0.f, p_hi = 0.f;
#pragma unroll
    for (int t = 0; t < 8; t++) {
        int c = n0 + t * 8 + qc * 2;
        float b0v = bp1[c], b1v = bp1[c + 1];
        float w0v = Wp2[c], w1v = Wp2[c + 1];
        p_lo += fmaxf(acc[t][0] + b0v, 0.f) * w0v + fmaxf(acc[t][1] + b1v, 0.f) * w1v;
        p_hi += fmaxf(acc[t][2] + b0v, 0.f) * w0v + fmaxf(acc[t][3] + b1v, 0.f) * w1v;
    }
    p_lo += __shfl_xor_sync(0xffffffffu, p_lo, 1);
    p_lo += __shfl_xor_sync(0xffffffffu, p_lo, 2);
    p_hi += __shfl_xor_sync(0xffffffffu, p_hi, 1);
    p_hi += __shfl_xor_sync(0xffffffffu, p_hi, 2);
    __syncthreads();
    float* s_head = (float*)smem_raw;  // 64 rows x 2 halves
    if (qc == 0) {
        s_head[(m0 + qr) * 2 + wx]     = p_lo;
        s_head[(m0 + qr + 8) * 2 + wx] = p_hi;
    }
    __syncthreads();
    if (tid < TILE_M) {
        int gr = row0 + tid;
        if (gr < n) {
            float z = s_head[tid * 2] + s_head[tid * 2 + 1] + bp2[0];
            out[gr] = 1.f / (1.f + expf(-z));
        }
    }
    // ---- state cleanup for the next run (this is the last kernel) ----
    int gt = blockIdx.x * 256 + tid;
    if (gt < Nn) d_deg[gt] = 0;
    if (gt < NB_SCAN) d_scan_state[gt] = 0ull;
    if (gt == 0) d_ticket = 0u;
    if (gt < 4 * NGg * Hh) { d_gsum[gt] = 0.f; d_gsq[gt] = 0.f; }
}

// ---------------- CSR aggregation + fused per-graph sum/sumsq -----------------
__global__ void agg_kernel(const __half* __restrict__ T, const float* __restrict__ bias,
                           float* __restrict__ A,
                           float* __restrict__ gsum, float* __restrict__ gsq) {
    __shared__ __align__(16) float s_red[2][8][132];
    __shared__ int s_same, s_g;
    int tid = threadIdx.x;
    int wid = tid >> 5;
    int lane = tid & 31;
    int node = blockIdx.x * 8 + wid;
    if (tid == 0) {
        int g0 = d_batch[blockIdx.x * 8];
        int g7 = d_batch[blockIdx.x * 8 + 7];
        s_same = (g0 == g7);
        s_g = g0;
    }
    int s = d_rowptr[node], e = d_rowptr[node + 1];
    float ax = 0.f, ay = 0.f, az = 0.f, aw = 0.f;
    int p = s;
    for (; p + 4 <= e; p += 4) {
        int2 e0 = d_colw[p], e1 = d_colw[p + 1], e2 = d_colw[p + 2], e3 = d_colw[p + 3];
        float w0 = __int_as_float(e0.y), w1 = __int_as_float(e1.y);
        float w2 = __int_as_float(e2.y), w3 = __int_as_float(e3.y);
        uint2 u0 = ((const uint2*)(T + (size_t)e0.x * 128))[lane];
        uint2 u1 = ((const uint2*)(T + (size_t)e1.x * 128))[lane];
        uint2 u2 = ((const uint2*)(T + (size_t)e2.x * 128))[lane];
        uint2 u3 = ((const uint2*)(T + (size_t)e3.x * 128))[lane];
        float2 a0 = __half22float2(*(__half2*)&u0.x), b0 = __half22float2(*(__half2*)&u0.y);
        float2 a1 = __half22float2(*(__half2*)&u1.x), b1 = __half22float2(*(__half2*)&u1.y);
        float2 a2 = __half22float2(*(__half2*)&u2.x), b2 = __half22float2(*(__half2*)&u2.y);
        float2 a3 = __half22float2(*(__half2*)&u3.x), b3 = __half22float2(*(__half2*)&u3.y);
        ax += w0 * a0.x + w1 * a1.x + w2 * a2.x + w3 * a3.x;
        ay += w0 * a0.y + w1 * a1.y + w2 * a2.y + w3 * a3.y;
        az += w0 * b0.x + w1 * b1.x + w2 * b2.x + w3 * b3.x;
        aw += w0 * b0.y + w1 * b1.y + w2 * b2.y + w3 * b3.y;
    }
    for (; p < e; p++) {
        int2 ec = d_colw[p];
        float w = __int_as_float(ec.y);
        uint2 u = ((const uint2*)(T + (size_t)ec.x * 128))[lane];
        float2 a = __half22float2(*(__half2*)&u.x), b = __half22float2(*(__half2*)&u.y);
        ax += w * a.x; ay += w * a.y; az += w * b.x; aw += w * b.y;
    }
    float ds = d_dis[node];
    float sl = ds * ds;
    uint2 ut = ((const uint2*)(T + (size_t)node * 128))[lane];
    float2 ta = __half22float2(*(__half2*)&ut.x), tb = __half22float2(*(__half2*)&ut.y);
    float4 bb = *(const float4*)&bias[lane * 4];
    float4 o;
    o.x = ax + sl * ta.x + bb.x;
    o.y = ay + sl * ta.y + bb.y;
    o.z = az + sl * tb.x + bb.z;
    o.w = aw + sl * tb.y + bb.w;
    *(float4*)&A[(size_t)node * 128 + lane * 4] = o;

    *(float4*)&s_red[0][wid][lane * 4] = o;
    float4 o2 = make_float4(o.x * o.x, o.y * o.y, o.z * o.z, o.w * o.w);
    *(float4*)&s_red[1][wid][lane * 4] = o2;
    __syncthreads();
    if (s_same) {
        if (tid < 128) {
            float t1 = 0.f, t2 = 0.f;
#pragma unroll
            for (int k = 0; k < 8; k++) { t1 += s_red[0][k][tid]; t2 += s_red[1][k][tid]; }
            atomicAdd(&gsum[s_g * 128 + tid], t1);
            atomicAdd(&gsq[s_g * 128 + tid], t2);
        }
    } else {
        int g = d_batch[node];
        atomicAdd(&gsum[g * 128 + lane * 4 + 0], o.x);
        atomicAdd(&gsum[g * 128 + lane * 4 + 1], o.y);
        atomicAdd(&gsum[g * 128 + lane * 4 + 2], o.z);
        atomicAdd(&gsum[g * 128 + lane * 4 + 3], o.w);
        atomicAdd(&gsq[g * 128 + lane * 4 + 0], o2.x);
        atomicAdd(&gsq[g * 128 + lane * 4 + 1], o2.y);
        atomicAdd(&gsq[g * 128 + lane * 4 + 2], o2.z);
        atomicAdd(&gsq[g * 128 + lane * 4 + 3], o2.w);
    }
}

// out = [in +] relu((A - alpha*mean)*rsqrt(var+eps)*gamma + beta)
template <int RES>
__global__ void final_kernel(const float* __restrict__ A, const float* __restrict__ in,
                             const float* __restrict__ alpha, const float* __restrict__ gamma,
                             const float* __restrict__ beta, float* __restrict__ out,
                             const float* __restrict__ gsum, const float* __restrict__ gsq) {
    int idx = blockIdx.x * blockDim.x + threadIdx.x;  // over N*32 float4s
    if (idx >= Nn * 32) return;
    int node = idx >> 5;
    int q = idx & 31;
    int g = d_batch[node];
    float inv = 1.f / d_gcntf[g];
    float4 a  = ((const float4*)A)[idx];
    float4 gs = *(const float4*)&gsum[g * 128 + q * 4];
    float4 gq = *(const float4*)&gsq[g * 128 + q * 4];
    float4 al = *(const float4*)&alpha[q * 4];
    float4 ga = *(const float4*)&gamma[q * 4];
    float4 be = *(const float4*)&beta[q * 4];
    float4 m, vv, o;
    m.x = gs.x * inv; m.y = gs.y * inv; m.z = gs.z * inv; m.w = gs.w * inv;
    vv.x = gq.x * inv - m.x * m.x * al.x * (2.f - al.x);
    vv.y = gq.y * inv - m.y * m.y * al.y * (2.f - al.y);
    vv.z = gq.z * inv - m.z * m.z * al.z * (2.f - al.z);
    vv.w = gq.w * inv - m.w * m.w * al.w * (2.f - al.w);
    o.x = fmaxf((a.x - al.x * m.x) * rsqrtf(vv.x + EPSc) * ga.x + be.x, 0.f);
    o.y = fmaxf((a.y - al.y * m.y) * rsqrtf(vv.y + EPSc) * ga.y + be.y, 0.f);
    o.z = fmaxf((a.z - al.z * m.z) * rsqrtf(vv.z + EPSc) * ga.z + be.z, 0.f);
    o.w = fmaxf((a.w - al.w * m.w) * rsqrtf(vv.w + EPSc) * ga.w + be.w, 0.f);
    if (RES) {
        float4 r = ((const float4*)in)[idx];
        o.x += r.x; o.y += r.y; o.z += r.z; o.w += r.w;
    }
    ((float4*)out)[idx] = o;
}

// ---------------- host orchestration ----------------
extern "C" void kernel_launch(void* const* d_in, const int* in_sizes, int n_in,
                              void* d_out, int out_size) {
    const float* x   = (const float*)d_in[0];
    const void*  ei  = d_in[1];
    const void*  bt  = d_in[2];
    const float* W1  = (const float*)d_in[3];
    const float* b1  = (const float*)d_in[4];
    const float* a1  = (const float*)d_in[5];
    const float* g1  = (const float*)d_in[6];
    const float* be1 = (const float*)d_in[7];
    const float* Wm  = (const float*)d_in[8];
    const float* bm  = (const float*)d_in[9];
    const float* am  = (const float*)d_in[10];
    const float* gm  = (const float*)d_in[11];
    const float* bem = (const float*)d_in[12];
    const float* WL  = (const float*)d_in[13];
    const float* bL  = (const float*)d_in[14];
    const float* aL  = (const float*)d_in[15];
    const float* gL  = (const float*)d_in[16];
    const float* beL = (const float*)d_in[17];
    const float* Wp1 = (const float*)d_in[18];
    const float* bp1 = (const float*)d_in[19];
    const float* Wp2 = (const float*)d_in[20];
    const float* bp2 = (const float*)d_in[21];
    float* out = (float*)d_out;

    float *HA, *HB, *A, *GS, *GQ;
    __half* Th;
    cudaGetSymbolAddress((void**)&HA, d_HA);
    cudaGetSymbolAddress((void**)&HB, d_HB);
    cudaGetSymbolAddress((void**)&Th, d_Th);
    cudaGetSymbolAddress((void**)&A,  d_A);
    cudaGetSymbolAddress((void**)&GS, d_gsum);
    cudaGetSymbolAddress((void**)&GQ, d_gsq);

    const int smem = GEMM_SMEM;
    cudaFuncSetAttribute(gemm_fp16_half_kernel, cudaFuncAttributeMaxDynamicSharedMemorySize, smem);
    cudaFuncSetAttribute(gemm_fp16_head_kernel, cudaFuncAttributeMaxDynamicSharedMemorySize, smem);

    // ---- preprocessing (3 launches; state zeroing done by previous run's tail) ----
    convert_hist_kernel<<<1024, 256>>>(ei, bt);
    scan_fused_kernel<<<NB_SCAN, 256>>>();
    scatter_kernel<<<(Ee + 255) / 256, 256>>>(ei);

    const int gemm_grid = (Nn + TILE_M - 1) / TILE_M;  // 782
    const int agg_grid  = Nn / 8;   // 6250, exact
    const int elem_grid = (Nn * 32 + 511) / 512;
    const int GL = NGg * Hh;

    // ---- layer 1: x -> HB ----
    gemm_fp16_half_kernel<<<gemm_grid, 256, smem>>>(x, W1, Th, Nn);
    agg_kernel<<<agg_grid, 256>>>(Th, b1, A, GS + 0 * GL, GQ + 0 * GL);
    final_kernel<0><<<elem_grid, 512>>>(A, nullptr, a1, g1, be1, HB, GS + 0 * GL, GQ + 0 * GL);

    // ---- mid layer 0 (residual): HB -> HA ----
    gemm_fp16_half_kernel<<<gemm_grid, 256, smem>>>(HB, Wm + 0 * 128 * 128, Th, Nn);
    agg_kernel<<<agg_grid, 256>>>(Th, bm + 0 * 128, A, GS + 1 * GL, GQ + 1 * GL);
    final_kernel<1><<<elem_grid, 512>>>(A, HB, am + 0 * 128, gm + 0 * 128, bem + 0 * 128, HA,
                                        GS + 1 * GL, GQ + 1 * GL);

    // ---- mid layer 1 (residual): HA -> HB ----
    gemm_fp16_half_kernel<<<gemm_grid, 256, smem>>>(HA, Wm + 1 * 128 * 128, Th, Nn);
    agg_kernel<<<agg_grid, 256>>>(Th, bm + 1 * 128, A, GS + 2 * GL, GQ + 2 * GL);
    final_kernel<1><<<elem_grid, 512>>>(A, HA, am + 1 * 128, gm + 1 * 128, bem + 1 * 128, HB,
                                        GS + 2 * GL, GQ + 2 * GL);

    // ---- last layer: HB -> HA ----
    gemm_fp16_half_kernel<<<gemm_grid, 256, smem>>>(HB, WL, Th, Nn);
    agg_kernel<<<agg_grid, 256>>>(Th, bL, A, GS + 3 * GL, GQ + 3 * GL);
    final_kernel<0><<<elem_grid, 512>>>(A, nullptr, aL, gL, beL, HA, GS + 3 * GL, GQ + 3 * GL);

    // ---- predictor: HA -> out (GEMM + fused head + state cleanup) ----
    gemm_fp16_head_kernel<<<gemm_grid, 256, smem>>>(HA, Wp1, bp1, Wp2, bp2, out, Nn);
}

// round 9
// speedup vs baseline: 1.7462x; 1.0714x over previous
#include <cuda_runtime.h>
#include <cuda_fp16.h>
#include <math.h>

#define Nn 50000
#define Hh 128
#define Ee 800000
#define NGg 64
#define EPSc 1e-5f
#define NB_SCAN 196   // ceil(50000/256)

// ---------------- device scratch (static globals; no allocation) ----------------
// All mutable state is zero at module load; the LAST kernel of each run
// (gemm_head epilogue) re-zeroes it, so every run starts clean.
__device__ int    d_batch[Nn];
__device__ int    d_deg[Nn];          // zeroed by head epilogue
__device__ float  d_dis[Nn];
__device__ int    d_rowptr[Nn + 1];
__device__ int    d_cursor[Nn];
__device__ int2   d_colw[Ee];
__device__ unsigned long long d_scan_state[NB_SCAN];  // zeroed by head epilogue
__device__ unsigned d_ticket;                          // zeroed by head epilogue
__device__ int    d_gstart[NGg + 1];
__device__ float  d_gcntf[NGg];
__device__ float  d_gsum[4 * NGg * Hh];  // zeroed by head epilogue
__device__ float  d_gsq[4 * NGg * Hh];   // zeroed by head epilogue
__device__ __half d_HAh[(size_t)Nn * Hh];   // fp16 hidden state A
__device__ __half d_HBh[(size_t)Nn * Hh];   // fp16 hidden state B
__device__ __half d_Th[(size_t)Nn * Hh];    // fp16 GEMM output (gather source)
__device__ float  d_A[(size_t)Nn * Hh];     // fp32 aggregated pre-norm
__device__ __half d_Wh[5 * Hh * Hh];        // fp16 weights: W1,Wm0,Wm1,WL,Wp1

__device__ __forceinline__ uint2 f4_to_h4(float4 v) {
    uint2 o;
    *(__half2*)&o.x = __floats2half2_rn(v.x, v.y);
    *(__half2*)&o.y = __floats2half2_rn(v.z, v.w);
    return o;
}

// ---------------- dtype detection (per-block, no global state) ----------------
__device__ __forceinline__ int detect_is64(const void* ei) {
    const long long* p = (const long long*)ei;
    int ok = 1;
#pragma unroll
    for (int k = 0; k < 16; k++) {
        long long v = p[k];
        if (v < 0 || v >= (long long)Nn) ok = 0;
    }
    return ok;
}

// ---------------- preprocessing ----------------

// convert the 5 weight matrices to fp16 (once per run)
__global__ void convert_w_kernel(const float* __restrict__ W1, const float* __restrict__ Wm,
                                 const float* __restrict__ WL, const float* __restrict__ Wp1) {
    int i = blockIdx.x * blockDim.x + threadIdx.x;  // over 5*4096 float4 groups
    if (i >= 5 * 4096) return;
    int m = i >> 12;
    int j = i & 4095;
    const float* src;
    switch (m) {
        case 0: src = W1; break;
        case 1: src = Wm; break;
        case 2: src = Wm + 16384; break;
        case 3: src = WL; break;
        default: src = Wp1; break;
    }
    ((uint2*)d_Wh)[i] = f4_to_h4(((const float4*)src)[j]);
}

__global__ void convert_hist_kernel(const void* ei, const void* bt) {
    __shared__ int s_is64;
    if (threadIdx.x == 0) s_is64 = detect_is64(ei);
    __syncthreads();
    int is64 = s_is64;
    int stride = gridDim.x * blockDim.x;
    for (int i = blockIdx.x * blockDim.x + threadIdx.x; i < Ee; i += stride) {
        int v = is64 ? (int)((const long long*)ei)[Ee + i] : ((const int*)ei)[Ee + i];
        atomicAdd(&d_deg[v], 1);
    }
    for (int i = blockIdx.x * blockDim.x + threadIdx.x; i < Nn; i += stride) {
        int v = is64 ? (int)((const long long*)bt)[i] : ((const int*)bt)[i];
        d_batch[i] = v;
    }
}

// decoupled-lookback scan of d_deg -> rowptr/cursor/dis + per-graph ranges
__global__ void scan_fused_kernel() {
    __shared__ unsigned sbid;
    __shared__ int s_excl;
    __shared__ int sh[256];
    if (threadIdx.x == 0) sbid = atomicAdd(&d_ticket, 1u);
    __syncthreads();
    int b = (int)sbid;
    int idx = b * 256 + threadIdx.x;
    int deg = (idx < Nn) ? d_deg[idx] : 0;
    sh[threadIdx.x] = deg;
    __syncthreads();
    for (int off = 1; off < 256; off <<= 1) {
        int u = 0;
        if (threadIdx.x >= off) u = sh[threadIdx.x - off];
        __syncthreads();
        if (threadIdx.x >= off) sh[threadIdx.x] += u;
        __syncthreads();
    }
    int incl = sh[threadIdx.x];
    int aggr = sh[255];
    if (threadIdx.x == 0) {
        if (b == 0) {
            atomicExch(&d_scan_state[0], (2ull << 32) | (unsigned)aggr);
            s_excl = 0;
        } else {
            atomicExch(&d_scan_state[b], (1ull << 32) | (unsigned)aggr);
            int excl = 0;
            int j = b - 1;
            while (true) {
                unsigned long long st;
                do { st = atomicAdd(&d_scan_state[j], 0ull); } while ((st >> 32) == 0ull);
                excl += (int)(unsigned)st;
                if ((st >> 32) == 2ull) break;
                j--;
            }
            atomicExch(&d_scan_state[b], (2ull << 32) | (unsigned)(excl + aggr));
            s_excl = excl;
        }
    }
    __syncthreads();
    int excl = s_excl;
    if (idx < Nn) {
        d_rowptr[idx + 1] = excl + incl;
        if (idx == 0) d_rowptr[0] = 0;
        d_cursor[idx] = excl + incl - deg;
        d_dis[idx] = rsqrtf((float)deg + 1.0f);
    }
    if (b == 0) {
        int t = threadIdx.x;
        if (t <= NGg) {
            int lo = 0, hi = Nn;
            while (lo < hi) {
                int mid = (lo + hi) >> 1;
                if (d_batch[mid] < t) lo = mid + 1; else hi = mid;
            }
            d_gstart[t] = lo;
        }
        __syncthreads();
        if (t < NGg) {
            int c = d_gstart[t + 1] - d_gstart[t];
            d_gcntf[t] = (c > 0) ? (float)c : 1.0f;
        }
    }
}

__global__ void scatter_kernel(const void* ei) {
    __shared__ int s_is64;
    if (threadIdx.x == 0) s_is64 = detect_is64(ei);
    __syncthreads();
    int i = blockIdx.x * blockDim.x + threadIdx.x;
    if (i >= Ee) return;
    int s, dd;
    if (s_is64) {
        s  = (int)((const long long*)ei)[i];
        dd = (int)((const long long*)ei)[Ee + i];
    } else {
        s  = ((const int*)ei)[i];
        dd = ((const int*)ei)[Ee + i];
    }
    int pos = atomicAdd(&d_cursor[dd], 1);
    d_colw[pos] = make_int2(s, __float_as_int(d_dis[s] * d_dis[dd]));
}

// ---------------- fp16 tensor-core GEMM (ldmatrix + mma.m16n8k16) -------------
// Y[n,128] = X[n,128] @ W[128,128]; fp16 operands, fp32 accumulate.
// 256 threads = 8 warps: wy=warp&3 -> rows wy*16..+15 ; wx=warp>>2 -> cols wx*64..+63
#define XPITCH 136
#define WPITCH 136
#define TILE_M 64
#define GEMM_SMEM ((TILE_M * XPITCH + 128 * WPITCH) * 2)

__device__ __forceinline__ void ldm_x4(unsigned& r0, unsigned& r1, unsigned& r2,
                                       unsigned& r3, unsigned addr) {
    asm volatile("ldmatrix.sync.aligned.m8n8.x4.shared.b16 {%0,%1,%2,%3}, [%4];"
                 : "=r"(r0), "=r"(r1), "=r"(r2), "=r"(r3) : "r"(addr));
}
__device__ __forceinline__ void ldm_x4t(unsigned& r0, unsigned& r1, unsigned& r2,
                                        unsigned& r3, unsigned addr) {
    asm volatile("ldmatrix.sync.aligned.m8n8.x4.trans.shared.b16 {%0,%1,%2,%3}, [%4];"
                 : "=r"(r0), "=r"(r1), "=r"(r2), "=r"(r3) : "r"(addr));
}

// stage X tile: fp32 source (layer 1) — convert
__device__ __forceinline__ void stage_X(const float* __restrict__ X, __half* Xs,
                                        int row0, int n, int tid) {
#pragma unroll
    for (int i = 0; i < 8; i++) {
        int idx = i * 256 + tid;
        int r = idx >> 5;
        int c = (idx & 31) * 4;
        float4 xv = make_float4(0.f, 0.f, 0.f, 0.f);
        if (row0 + r < n) xv = *(const float4*)&X[(size_t)(row0 + r) * 128 + c];
        *(uint2*)&Xs[r * XPITCH + c] = f4_to_h4(xv);
    }
}
// stage X tile: fp16 source — straight copy (uint4 = 8 halves)
__device__ __forceinline__ void stage_X(const __half* __restrict__ X, __half* Xs,
                                        int row0, int n, int tid) {
#pragma unroll
    for (int i = 0; i < 4; i++) {
        int idx = i * 256 + tid;
        int r = idx >> 4;
        int c = (idx & 15) * 8;
        uint4 v = make_uint4(0u, 0u, 0u, 0u);
        if (row0 + r < n) v = *(const uint4*)&X[(size_t)(row0 + r) * 128 + c];
        *(uint4*)&Xs[r * XPITCH + c] = v;
    }
}
// stage W (always fp16): 128x128 halves, straight copy
__device__ __forceinline__ void stage_W(const __half* __restrict__ W, __half* Ws, int tid) {
#pragma unroll
    for (int i = 0; i < 8; i++) {
        int idx = i * 256 + tid;
        int r = idx >> 4;
        int c = (idx & 15) * 8;
        *(uint4*)&Ws[r * WPITCH + c] = *(const uint4*)&W[r * 128 + c];
    }
}

#define FP16_GEMM_CORE()                                                          \
    extern __shared__ __align__(16) char smem_raw[];                              \
    __half* Xs = (__half*)smem_raw;                                               \
    __half* Ws = Xs + TILE_M * XPITCH;                                            \
    const int tid = threadIdx.x;                                                  \
    const int row0 = blockIdx.x * TILE_M;                                         \
    stage_W(W, Ws, tid);                                                          \
    stage_X(X, Xs, row0, n, tid);                                                 \
    __syncthreads();                                                              \
    const int warp = tid >> 5;                                                    \
    const int lane = tid & 31;                                                    \
    const int qr = lane >> 2;                                                     \
    const int qc = lane & 3;                                                      \
    const int wy = warp & 3;                                                      \
    const int wx = warp >> 2;                                                     \
    const int m0 = wy * 16;                                                       \
    const int n0 = wx * 64;                                                       \
    const int trow = lane & 7;                                                    \
    const int tsel = lane >> 3;                                                   \
    unsigned xs_b = (unsigned)__cvta_generic_to_shared(Xs);                       \
    unsigned ws_b = (unsigned)__cvta_generic_to_shared(Ws);                       \
    unsigned a_addr = xs_b +                                                      \
        ((m0 + trow + 8 * (tsel & 1)) * XPITCH + 8 * (tsel >> 1)) * 2;            \
    unsigned b_addr = ws_b +                                                      \
        ((trow + 8 * (tsel & 1)) * WPITCH + n0 + 8 * (tsel >> 1)) * 2;            \
    float acc[8][4];                                                              \
    _Pragma("unroll")                                                             \
    for (int t = 0; t < 8; t++) {                                                 \
        acc[t][0] = 0.f; acc[t][1] = 0.f; acc[t][2] = 0.f; acc[t][3] = 0.f;       \
    }                                                                             \
    _Pragma("unroll")                                                             \
    for (int ks = 0; ks < 8; ks++) {                                              \
        unsigned a0, a1, a2, a3;                                                  \
        ldm_x4(a0, a1, a2, a3, a_addr + ks * 32);                                 \
        _Pragma("unroll")                                                         \
        for (int tp = 0; tp < 4; tp++) {                                          \
            unsigned b0, b1, b2, b3;                                              \
            ldm_x4t(b0, b1, b2, b3, b_addr + ks * (16 * WPITCH * 2) + tp * 32);   \
            asm volatile(                                                         \
                "mma.sync.aligned.m16n8k16.row.col.f32.f16.f16.f32 "              \
                "{%0,%1,%2,%3}, {%4,%5,%6,%7}, {%8,%9}, {%0,%1,%2,%3};"           \
                : "+f"(acc[2 * tp][0]), "+f"(acc[2 * tp][1]),                     \
                  "+f"(acc[2 * tp][2]), "+f"(acc[2 * tp][3])                      \
                : "r"(a0), "r"(a1), "r"(a2), "r"(a3), "r"(b0), "r"(b1));          \
            asm volatile(                                                         \
                "mma.sync.aligned.m16n8k16.row.col.f32.f16.f16.f32 "              \
                "{%0,%1,%2,%3}, {%4,%5,%6,%7}, {%8,%9}, {%0,%1,%2,%3};"           \
                : "+f"(acc[2 * tp + 1][0]), "+f"(acc[2 * tp + 1][1]),             \
                  "+f"(acc[2 * tp + 1][2]), "+f"(acc[2 * tp + 1][3])              \
                : "r"(a0), "r"(a1), "r"(a2), "r"(a3), "r"(b2), "r"(b3));          \
        }                                                                         \
    }                                                                             \
    const int r_lo = row0 + m0 + qr;                                              \
    const int r_hi = r_lo + 8;

// fp16-output GEMM (feeds edge gather); input fp32 or fp16
template <typename TIn>
__global__ __launch_bounds__(256) void gemm_fp16_half_kernel(
    const TIn* __restrict__ X, const __half* __restrict__ W,
    __half* __restrict__ Y, int n) {
    FP16_GEMM_CORE()
    if (r_lo < n) {
#pragma unroll
        for (int t = 0; t < 8; t++)
            *(__half2*)&Y[(size_t)r_lo * 128 + n0 + t * 8 + qc * 2] =
                __floats2half2_rn(acc[t][0], acc[t][1]);
    }
    if (r_hi < n) {
#pragma unroll
        for (int t = 0; t < 8; t++)
            *(__half2*)&Y[(size_t)r_hi * 128 + n0 + t * 8 + qc * 2] =
                __floats2half2_rn(acc[t][2], acc[t][3]);
    }
}

// final GEMM with fused predictor head + end-of-run state cleanup (fp16 input).
__global__ __launch_bounds__(256) void gemm_fp16_head_kernel(
    const __half* __restrict__ X, const __half* __restrict__ W,
    const float* __restrict__ bp1, const float* __restrict__ Wp2,
    const float* __restrict__ bp2, float* __restrict__ out, int n) {
    FP16_GEMM_CORE()
    float p_lo = 0.f, p_hi = 0.f;
#pragma unroll
    for (int t = 0; t < 8; t++) {
        int c = n0 + t * 8 + qc * 2;
        float b0v = bp1[c], b1v = bp1[c + 1];
        float w0v = Wp2[c], w1v = Wp2[c + 1];
        p_lo += fmaxf(acc[t][0] + b0v, 0.f) * w0v + fmaxf(acc[t][1] + b1v, 0.f) * w1v;
        p_hi += fmaxf(acc[t][2] + b0v, 0.f) * w0v + fmaxf(acc[t][3] + b1v, 0.f) * w1v;
    }
    p_lo += __shfl_xor_sync(0xffffffffu, p_lo, 1);
    p_lo += __shfl_xor_sync(0xffffffffu, p_lo, 2);
    p_hi += __shfl_xor_sync(0xffffffffu, p_hi, 1);
    p_hi += __shfl_xor_sync(0xffffffffu, p_hi, 2);
    __syncthreads();
    float* s_head = (float*)smem_raw;  // 64 rows x 2 halves
    if (qc == 0) {
        s_head[(m0 + qr) * 2 + wx]     = p_lo;
        s_head[(m0 + qr + 8) * 2 + wx] = p_hi;
    }
    __syncthreads();
    if (tid < TILE_M) {
        int gr = row0 + tid;
        if (gr < n) {
            float z = s_head[tid * 2] + s_head[tid * 2 + 1] + bp2[0];
            out[gr] = 1.f / (1.f + expf(-z));
        }
    }
    // ---- state cleanup for the next run (this is the last kernel) ----
    int gt = blockIdx.x * 256 + tid;
    if (gt < Nn) d_deg[gt] = 0;
    if (gt < NB_SCAN) d_scan_state[gt] = 0ull;
    if (gt == 0) d_ticket = 0u;
    if (gt < 4 * NGg * Hh) { d_gsum[gt] = 0.f; d_gsq[gt] = 0.f; }
}

// ---------------- CSR aggregation + fused per-graph sum/sumsq -----------------
__global__ void agg_kernel(const __half* __restrict__ T, const float* __restrict__ bias,
                           float* __restrict__ A,
                           float* __restrict__ gsum, float* __restrict__ gsq) {
    __shared__ __align__(16) float s_red[2][8][132];
    __shared__ int s_same, s_g;
    int tid = threadIdx.x;
    int wid = tid >> 5;
    int lane = tid & 31;
    int node = blockIdx.x * 8 + wid;
    if (tid == 0) {
        int g0 = d_batch[blockIdx.x * 8];
        int g7 = d_batch[blockIdx.x * 8 + 7];
        s_same = (g0 == g7);
        s_g = g0;
    }
    int s = d_rowptr[node], e = d_rowptr[node + 1];
    float ax = 0.f, ay = 0.f, az = 0.f, aw = 0.f;
    int p = s;
    for (; p + 4 <= e; p += 4) {
        int2 e0 = d_colw[p], e1 = d_colw[p + 1], e2 = d_colw[p + 2], e3 = d_colw[p + 3];
        float w0 = __int_as_float(e0.y), w1 = __int_as_float(e1.y);
        float w2 = __int_as_float(e2.y), w3 = __int_as_float(e3.y);
        uint2 u0 = ((const uint2*)(T + (size_t)e0.x * 128))[lane];
        uint2 u1 = ((const uint2*)(T + (size_t)e1.x * 128))[lane];
        uint2 u2 = ((const uint2*)(T + (size_t)e2.x * 128))[lane];
        uint2 u3 = ((const uint2*)(T + (size_t)e3.x * 128))[lane];
        float2 a0 = __half22float2(*(__half2*)&u0.x), b0 = __half22float2(*(__half2*)&u0.y);
        float2 a1 = __half22float2(*(__half2*)&u1.x), b1 = __half22float2(*(__half2*)&u1.y);
        float2 a2 = __half22float2(*(__half2*)&u2.x), b2 = __half22float2(*(__half2*)&u2.y);
        float2 a3 = __half22float2(*(__half2*)&u3.x), b3 = __half22float2(*(__half2*)&u3.y);
        ax += w0 * a0.x + w1 * a1.x + w2 * a2.x + w3 * a3.x;
        ay += w0 * a0.y + w1 * a1.y + w2 * a2.y + w3 * a3.y;
        az += w0 * b0.x + w1 * b1.x + w2 * b2.x + w3 * b3.x;
        aw += w0 * b0.y + w1 * b1.y + w2 * b2.y + w3 * b3.y;
    }
    for (; p < e; p++) {
        int2 ec = d_colw[p];
        float w = __int_as_float(ec.y);
        uint2 u = ((const uint2*)(T + (size_t)ec.x * 128))[lane];
        float2 a = __half22float2(*(__half2*)&u.x), b = __half22float2(*(__half2*)&u.y);
        ax += w * a.x; ay += w * a.y; az += w * b.x; aw += w * b.y;
    }
    float ds = d_dis[node];
    float sl = ds * ds;
    uint2 ut = ((const uint2*)(T + (size_t)node * 128))[lane];
    float2 ta = __half22float2(*(__half2*)&ut.x), tb = __half22float2(*(__half2*)&ut.y);
    float4 bb = *(const float4*)&bias[lane * 4];
    float4 o;
    o.x = ax + sl * ta.x + bb.x;
    o.y = ay + sl * ta.y + bb.y;
    o.z = az + sl * tb.x + bb.z;
    o.w = aw + sl * tb.y + bb.w;
    *(float4*)&A[(size_t)node * 128 + lane * 4] = o;

    *(float4*)&s_red[0][wid][lane * 4] = o;
    float4 o2 = make_float4(o.x * o.x, o.y * o.y, o.z * o.z, o.w * o.w);
    *(float4*)&s_red[1][wid][lane * 4] = o2;
    __syncthreads();
    if (s_same) {
        if (tid < 128) {
            float t1 = 0.f, t2 = 0.f;
#pragma unroll
            for (int k = 0; k < 8; k++) { t1 += s_red[0][k][tid]; t2 += s_red[1][k][tid]; }
            atomicAdd(&gsum[s_g * 128 + tid], t1);
            atomicAdd(&gsq[s_g * 128 + tid], t2);
        }
    } else {
        int g = d_batch[node];
        atomicAdd(&gsum[g * 128 + lane * 4 + 0], o.x);
        atomicAdd(&gsum[g * 128 + lane * 4 + 1], o.y);
        atomicAdd(&gsum[g * 128 + lane * 4 + 2], o.z);
        atomicAdd(&gsum[g * 128 + lane * 4 + 3], o.w);
        atomicAdd(&gsq[g * 128 + lane * 4 + 0], o2.x);
        atomicAdd(&gsq[g * 128 + lane * 4 + 1], o2.y);
        atomicAdd(&gsq[g * 128 + lane * 4 + 2], o2.z);
        atomicAdd(&gsq[g * 128 + lane * 4 + 3], o2.w);
    }
}

// out(fp16) = [in(fp16) +] relu((A - alpha*mean)*rsqrt(var+eps)*gamma + beta)
template <int RES>
__global__ void final_kernel(const float* __restrict__ A, const __half* __restrict__ in,
                             const float* __restrict__ alpha, const float* __restrict__ gamma,
                             const float* __restrict__ beta, __half* __restrict__ out,
                             const float* __restrict__ gsum, const float* __restrict__ gsq) {
    int idx = blockIdx.x * blockDim.x + threadIdx.x;  // over N*32 groups of 4
    if (idx >= Nn * 32) return;
    int node = idx >> 5;
    int q = idx & 31;
    int g = d_batch[node];
    float inv = 1.f / d_gcntf[g];
    float4 a  = ((const float4*)A)[idx];
    float4 gs = *(const float4*)&gsum[g * 128 + q * 4];
    float4 gq = *(const float4*)&gsq[g * 128 + q * 4];
    float4 al = *(const float4*)&alpha[q * 4];
    float4 ga = *(const float4*)&gamma[q * 4];
    float4 be = *(const float4*)&beta[q * 4];
    float4 m, vv, o;
    m.x = gs.x * inv; m.y = gs.y * inv; m.z = gs.z * inv; m.w = gs.w * inv;
    vv.x = gq.x * inv - m.x * m.x * al.x * (2.f - al.x);
    vv.y = gq.y * inv - m.y * m.y * al.y * (2.f - al.y);
    vv.z = gq.z * inv - m.z * m.z * al.z * (2.f - al.z);
    vv.w = gq.w * inv - m.w * m.w * al.w * (2.f - al.w);
    o.x = fmaxf((a.x - al.x * m.x) * rsqrtf(vv.x + EPSc) * ga.x + be.x, 0.f);
    o.y = fmaxf((a.y - al.y * m.y) * rsqrtf(vv.y + EPSc) * ga.y + be.y, 0.f);
    o.z = fmaxf((a.z - al.z * m.z) * rsqrtf(vv.z + EPSc) * ga.z + be.z, 0.f);
    o.w = fmaxf((a.w - al.w * m.w) * rsqrtf(vv.w + EPSc) * ga.w + be.w, 0.f);
    if (RES) {
        uint2 r = ((const uint2*)in)[idx];
        float2 r0 = __half22float2(*(__half2*)&r.x);
        float2 r1 = __half22float2(*(__half2*)&r.y);
        o.x += r0.x; o.y += r0.y; o.z += r1.x; o.w += r1.y;
    }
    ((uint2*)out)[idx] = f4_to_h4(o);
}

// ---------------- host orchestration ----------------
extern "C" void kernel_launch(void* const* d_in, const int* in_sizes, int n_in,
                              void* d_out, int out_size) {
    const float* x   = (const float*)d_in[0];
    const void*  ei  = d_in[1];
    const void*  bt  = d_in[2];
    const float* W1  = (const float*)d_in[3];
    const float* b1  = (const float*)d_in[4];
    const float* a1  = (const float*)d_in[5];
    const float* g1  = (const float*)d_in[6];
    const float* be1 = (const float*)d_in[7];
    const float* Wm  = (const float*)d_in[8];
    const float* bm  = (const float*)d_in[9];
    const float* am  = (const float*)d_in[10];
    const float* gm  = (const float*)d_in[11];
    const float* bem = (const float*)d_in[12];
    const float* WL  = (const float*)d_in[13];
    const float* bL  = (const float*)d_in[14];
    const float* aL  = (const float*)d_in[15];
    const float* gL  = (const float*)d_in[16];
    const float* beL = (const float*)d_in[17];
    const float* Wp1 = (const float*)d_in[18];
    const float* bp1 = (const float*)d_in[19];
    const float* Wp2 = (const float*)d_in[20];
    const float* bp2 = (const float*)d_in[21];
    float* out = (float*)d_out;

    float *A, *GS, *GQ;
    __half *HAh, *HBh, *Th, *Wh;
    cudaGetSymbolAddress((void**)&HAh, d_HAh);
    cudaGetSymbolAddress((void**)&HBh, d_HBh);
    cudaGetSymbolAddress((void**)&Th,  d_Th);
    cudaGetSymbolAddress((void**)&A,   d_A);
    cudaGetSymbolAddress((void**)&GS,  d_gsum);
    cudaGetSymbolAddress((void**)&GQ,  d_gsq);
    cudaGetSymbolAddress((void**)&Wh,  d_Wh);

    const int smem = GEMM_SMEM;
    cudaFuncSetAttribute(gemm_fp16_half_kernel<float>,  cudaFuncAttributeMaxDynamicSharedMemorySize, smem);
    cudaFuncSetAttribute(gemm_fp16_half_kernel<__half>, cudaFuncAttributeMaxDynamicSharedMemorySize, smem);
    cudaFuncSetAttribute(gemm_fp16_head_kernel, cudaFuncAttributeMaxDynamicSharedMemorySize, smem);

    // ---- preprocessing (4 launches; state zeroing done by previous run's tail) ----
    convert_w_kernel<<<80, 256>>>(W1, Wm, WL, Wp1);
    convert_hist_kernel<<<1024, 256>>>(ei, bt);
    scan_fused_kernel<<<NB_SCAN, 256>>>();
    scatter_kernel<<<(Ee + 255) / 256, 256>>>(ei);

    const int gemm_grid = (Nn + TILE_M - 1) / TILE_M;  // 782
    const int agg_grid  = Nn / 8;   // 6250, exact
    const int elem_grid = (Nn * 32 + 511) / 512;
    const int GL = NGg * Hh;
    const int WSZ = Hh * Hh;

    // ---- layer 1: x (fp32) -> HBh ----
    gemm_fp16_half_kernel<float><<<gemm_grid, 256, smem>>>(x, Wh + 0 * WSZ, Th, Nn);
    agg_kernel<<<agg_grid, 256>>>(Th, b1, A, GS + 0 * GL, GQ + 0 * GL);
    final_kernel<0><<<elem_grid, 512>>>(A, nullptr, a1, g1, be1, HBh, GS + 0 * GL, GQ + 0 * GL);

    // ---- mid layer 0 (residual): HBh -> HAh ----
    gemm_fp16_half_kernel<__half><<<gemm_grid, 256, smem>>>(HBh, Wh + 1 * WSZ, Th, Nn);
    agg_kernel<<<agg_grid, 256>>>(Th, bm + 0 * 128, A, GS + 1 * GL, GQ + 1 * GL);
    final_kernel<1><<<elem_grid, 512>>>(A, HBh, am + 0 * 128, gm + 0 * 128, bem + 0 * 128, HAh,
                                        GS + 1 * GL, GQ + 1 * GL);

    // ---- mid layer 1 (residual): HAh -> HBh ----
    gemm_fp16_half_kernel<__half><<<gemm_grid, 256, smem>>>(HAh, Wh + 2 * WSZ, Th, Nn);
    agg_kernel<<<agg_grid, 256>>>(Th, bm + 1 * 128, A, GS + 2 * GL, GQ + 2 * GL);
    final_kernel<1><<<elem_grid, 512>>>(A, HAh, am + 1 * 128, gm + 1 * 128, bem + 1 * 128, HBh,
                                        GS + 2 * GL, GQ + 2 * GL);

    // ---- last layer: HBh -> HAh ----
    gemm_fp16_half_kernel<__half><<<gemm_grid, 256, smem>>>(HBh, Wh + 3 * WSZ, Th, Nn);
    agg_kernel<<<agg_grid, 256>>>(Th, bL, A, GS + 3 * GL, GQ + 3 * GL);
    final_kernel<0><<<elem_grid, 512>>>(A, nullptr, aL, gL, beL, HAh, GS + 3 * GL, GQ + 3 * GL);

    // ---- predictor: HAh -> out (GEMM + fused head + state cleanup) ----
    gemm_fp16_head_kernel<<<gemm_grid, 256, smem>>>(HAh, Wh + 4 * WSZ, bp1, Wp2, bp2, out, Nn);
}